// round 1
// baseline (speedup 1.0000x reference)
#include <cuda_runtime.h>
#include <math.h>

#define N_FR   16384
#define D_EMB  1024
#define A_DIM  2048
#define H_H    8
#define B_SEG  64
#define DH     (D_EMB*H_H)   // 8192

// ---------------- scratch (static device globals; no allocation) -----------
__device__ float g_hpart[4][N_FR*H_H];        // partial h over a-splits (2 MB)
__device__ float g_h[N_FR*H_H];               // combined logits (512 KB)
__device__ float g_attn[N_FR*H_H];            // softmax weights (512 KB)
__device__ float g_obdh[B_SEG*DH];            // pooled [B, D*H] (2 MB)
__device__ float g_outpart[8][B_SEG*D_EMB];   // k-split partials of final GEMM (2 MB)
__device__ int   g_segstart[B_SEG+1];

// ---------------- 0: prefix sum of segment lengths --------------------------
__global__ void k_prefix(const int* __restrict__ seg) {
    if (threadIdx.x == 0) {
        int acc = 0;
        g_segstart[0] = 0;
        for (int i = 0; i < B_SEG; i++) { acc += seg[i]; g_segstart[i+1] = acc; }
    }
}

// ---------------- 1: h = relu(x @ w1) @ w2, fused ---------------------------
// grid (N/64, 4), block 256. Block computes 64 rows x 512 a-cols of relu(x@w1)
// in 8 tiles of 64, contracting each tile with w2 into an 8-wide accumulator.
__global__ __launch_bounds__(256) void k_gemm1(
    const float* __restrict__ x, const float* __restrict__ w1,
    const float* __restrict__ w2)
{
    __shared__ float Xs[16][72];
    __shared__ float Ws[16][72];
    __shared__ float Cs[64][72];
    __shared__ float W2s[64][8];

    const int tid = threadIdx.x;
    const int tx = tid & 15, ty = tid >> 4;
    const int n0 = blockIdx.x * 64;
    const int abase = blockIdx.y * 512;
    const int er = tid >> 3, eh = tid & 7;

    float hacc0 = 0.f, hacc1 = 0.f;

    for (int at = 0; at < 8; at++) {
        const int a0 = abase + at * 64;
        float acc[4][4];
        #pragma unroll
        for (int i = 0; i < 4; i++)
            #pragma unroll
            for (int j = 0; j < 4; j++) acc[i][j] = 0.f;

        for (int kc = 0; kc < 64; kc++) {
            const int k0 = kc * 16;
            {   // load X tile (64 rows x 16 k), transposed into Xs[k][row]
                const int row = tid >> 2, q = tid & 3;
                float4 v = *(const float4*)&x[(size_t)(n0 + row) * D_EMB + k0 + q * 4];
                Xs[q*4+0][row] = v.x; Xs[q*4+1][row] = v.y;
                Xs[q*4+2][row] = v.z; Xs[q*4+3][row] = v.w;
            }
            {   // load W1 tile (16 k x 64 a)
                const int row = tid >> 4, q = tid & 15;
                float4 v = *(const float4*)&w1[(size_t)(k0 + row) * A_DIM + a0 + q * 4];
                *(float4*)&Ws[row][q * 4] = v;
            }
            __syncthreads();
            #pragma unroll
            for (int k = 0; k < 16; k++) {
                float4 xv = *(const float4*)&Xs[k][ty * 4];
                float4 wv = *(const float4*)&Ws[k][tx * 4];
                float xr[4] = {xv.x, xv.y, xv.z, xv.w};
                float wr[4] = {wv.x, wv.y, wv.z, wv.w};
                #pragma unroll
                for (int i = 0; i < 4; i++)
                    #pragma unroll
                    for (int j = 0; j < 4; j++)
                        acc[i][j] = fmaf(xr[i], wr[j], acc[i][j]);
            }
            __syncthreads();
        }

        // relu -> Cs
        #pragma unroll
        for (int i = 0; i < 4; i++)
            #pragma unroll
            for (int j = 0; j < 4; j++)
                Cs[ty*4 + i][tx*4 + j] = fmaxf(acc[i][j], 0.f);
        {   // load w2 tile (64 a x 8 h)
            const int aa = tid >> 3, hh = tid & 7;
            W2s[aa][hh]      = w2[(size_t)(a0 + aa) * H_H + hh];
            W2s[aa + 32][hh] = w2[(size_t)(a0 + 32 + aa) * H_H + hh];
        }
        __syncthreads();

        float s0 = 0.f, s1 = 0.f;
        #pragma unroll
        for (int a = 0; a < 64; a++) {
            s0 = fmaf(Cs[er][a],      W2s[a][eh], s0);
            s1 = fmaf(Cs[er + 32][a], W2s[a][eh], s1);
        }
        hacc0 += s0; hacc1 += s1;
        __syncthreads();
    }

    g_hpart[blockIdx.y][(size_t)(n0 + er) * H_H + eh]      = hacc0;
    g_hpart[blockIdx.y][(size_t)(n0 + er + 32) * H_H + eh] = hacc1;
}

// ---------------- 2: per-segment softmax ------------------------------------
__global__ __launch_bounds__(256) void k_softmax() {
    const int b = blockIdx.x;
    const int tid = threadIdx.x;
    const int start = g_segstart[b];
    const int len = g_segstart[b+1] - start;

    __shared__ float red[256 * H_H];
    __shared__ float mval[H_H], sval[H_H];

    // pass 0: combine partials + local max
    float lm[H_H];
    #pragma unroll
    for (int h = 0; h < H_H; h++) lm[h] = -1e30f;
    for (int r = tid; r < len; r += 256) {
        const int n = start + r;
        #pragma unroll
        for (int h = 0; h < H_H; h++) {
            float v = g_hpart[0][n*H_H+h] + g_hpart[1][n*H_H+h]
                    + g_hpart[2][n*H_H+h] + g_hpart[3][n*H_H+h];
            g_h[n*H_H+h] = v;
            lm[h] = fmaxf(lm[h], v);
        }
    }
    #pragma unroll
    for (int h = 0; h < H_H; h++) red[tid*H_H+h] = lm[h];
    __syncthreads();
    for (int off = 128; off > 0; off >>= 1) {
        if (tid < off)
            #pragma unroll
            for (int h = 0; h < H_H; h++)
                red[tid*H_H+h] = fmaxf(red[tid*H_H+h], red[(tid+off)*H_H+h]);
        __syncthreads();
    }
    if (tid < H_H) mval[tid] = red[tid];
    __syncthreads();

    // pass 1: sum of exp
    float ls[H_H];
    #pragma unroll
    for (int h = 0; h < H_H; h++) ls[h] = 0.f;
    for (int r = tid; r < len; r += 256) {
        const int n = start + r;
        #pragma unroll
        for (int h = 0; h < H_H; h++)
            ls[h] += expf(g_h[n*H_H+h] - mval[h]);
    }
    #pragma unroll
    for (int h = 0; h < H_H; h++) red[tid*H_H+h] = ls[h];
    __syncthreads();
    for (int off = 128; off > 0; off >>= 1) {
        if (tid < off)
            #pragma unroll
            for (int h = 0; h < H_H; h++)
                red[tid*H_H+h] += red[(tid+off)*H_H+h];
        __syncthreads();
    }
    if (tid < H_H) sval[tid] = red[tid];
    __syncthreads();

    // pass 2: write attn
    float inv[H_H];
    #pragma unroll
    for (int h = 0; h < H_H; h++) inv[h] = 1.f / sval[h];
    for (int r = tid; r < len; r += 256) {
        const int n = start + r;
        #pragma unroll
        for (int h = 0; h < H_H; h++)
            g_attn[n*H_H+h] = expf(g_h[n*H_H+h] - mval[h]) * inv[h];
    }
}

// ---------------- 3: pooling: obdh = x^T@attn per segment; out_segment mean -
// grid (B, 4), block 256. Block (b, dc) handles d in [dc*256, dc*256+256).
__global__ __launch_bounds__(256) void k_pool(
    const float* __restrict__ x, float* __restrict__ out)
{
    const int b = blockIdx.x;
    const int d = blockIdx.y * 256 + threadIdx.x;
    const int start = g_segstart[b];
    const int len = g_segstart[b+1] - start;

    __shared__ float sat[32][H_H];
    float acc[H_H];
    #pragma unroll
    for (int h = 0; h < H_H; h++) acc[h] = 0.f;
    float ssum = 0.f;

    for (int r0 = 0; r0 < len; r0 += 32) {
        const int cnt = min(32, len - r0);
        if (threadIdx.x < cnt * H_H) {
            const int rr = threadIdx.x >> 3, hh = threadIdx.x & 7;
            sat[rr][hh] = g_attn[(size_t)(start + r0 + rr) * H_H + hh];
        }
        __syncthreads();
        for (int rr = 0; rr < cnt; rr++) {
            const float xv = x[(size_t)(start + r0 + rr) * D_EMB + d];
            ssum += xv;
            #pragma unroll
            for (int h = 0; h < H_H; h++)
                acc[h] = fmaf(xv, sat[rr][h], acc[h]);
        }
        __syncthreads();
    }
    #pragma unroll
    for (int h = 0; h < H_H; h++)
        g_obdh[(size_t)b * DH + d * H_H + h] = acc[h];
    out[B_SEG * D_EMB + (size_t)b * D_EMB + d] = ssum / (float)len;
}

// ---------------- 4: attn gram, [B,8,8] -------------------------------------
__global__ void k_gram(float* __restrict__ out) {
    const int b = blockIdx.x;
    const int tid = threadIdx.x;  // 64
    const int i = tid >> 3, j = tid & 7;
    const int start = g_segstart[b];
    const int len = g_segstart[b+1] - start;
    float acc = 0.f;
    for (int r = 0; r < len; r++) {
        const float* a = &g_attn[(size_t)(start + r) * H_H];
        acc = fmaf(a[i], a[j], acc);
    }
    out[2 * B_SEG * D_EMB + b * 64 + tid] = acc;
}

// ---------------- 5: final GEMM: out = obdh[64,8192] @ w_post[8192,1024] ----
// grid (16 j-tiles, 8 k-splits), block 256; 64x64 tile, partials then reduce.
__global__ __launch_bounds__(256) void k_post(const float* __restrict__ wp) {
    __shared__ float As[16][72];
    __shared__ float Ws[16][72];
    const int tid = threadIdx.x;
    const int tx = tid & 15, ty = tid >> 4;
    const int j0 = blockIdx.x * 64;
    const int ks = blockIdx.y;
    const int kbase = ks * 1024;

    float acc[4][4];
    #pragma unroll
    for (int i = 0; i < 4; i++)
        #pragma unroll
        for (int j = 0; j < 4; j++) acc[i][j] = 0.f;

    for (int kc = 0; kc < 64; kc++) {
        const int k0 = kbase + kc * 16;
        {   // obdh tile: 64 b-rows x 16 k, transposed
            const int row = tid >> 2, q = tid & 3;
            float4 v = *(const float4*)&g_obdh[(size_t)row * DH + k0 + q * 4];
            As[q*4+0][row] = v.x; As[q*4+1][row] = v.y;
            As[q*4+2][row] = v.z; As[q*4+3][row] = v.w;
        }
        {   // w_post tile: 16 k x 64 j
            const int row = tid >> 4, q = tid & 15;
            float4 v = *(const float4*)&wp[(size_t)(k0 + row) * D_EMB + j0 + q * 4];
            *(float4*)&Ws[row][q * 4] = v;
        }
        __syncthreads();
        #pragma unroll
        for (int k = 0; k < 16; k++) {
            float4 av = *(const float4*)&As[k][ty * 4];
            float4 wv = *(const float4*)&Ws[k][tx * 4];
            float ar[4] = {av.x, av.y, av.z, av.w};
            float wr[4] = {wv.x, wv.y, wv.z, wv.w};
            #pragma unroll
            for (int i = 0; i < 4; i++)
                #pragma unroll
                for (int j = 0; j < 4; j++)
                    acc[i][j] = fmaf(ar[i], wr[j], acc[i][j]);
        }
        __syncthreads();
    }
    #pragma unroll
    for (int i = 0; i < 4; i++)
        #pragma unroll
        for (int j = 0; j < 4; j++)
            g_outpart[ks][(size_t)(ty*4 + i) * D_EMB + j0 + tx*4 + j] = acc[i][j];
}

__global__ void k_redout(float* __restrict__ out) {
    const int i = blockIdx.x * 256 + threadIdx.x;  // 65536 total
    float s = 0.f;
    #pragma unroll
    for (int p = 0; p < 8; p++) s += g_outpart[p][i];
    out[i] = s;
}

// ---------------- launch -----------------------------------------------------
extern "C" void kernel_launch(void* const* d_in, const int* in_sizes, int n_in,
                              void* d_out, int out_size)
{
    const float* x   = (const float*)d_in[0];
    const int*   seg = (const int*)  d_in[1];
    const float* w1  = (const float*)d_in[2];
    const float* w2  = (const float*)d_in[3];
    const float* wp  = (const float*)d_in[4];
    float* out = (float*)d_out;

    k_prefix <<<1, 32>>>(seg);
    k_gemm1  <<<dim3(N_FR/64, 4), 256>>>(x, w1, w2);
    k_softmax<<<B_SEG, 256>>>();
    k_pool   <<<dim3(B_SEG, 4), 256>>>(x, out);
    k_gram   <<<B_SEG, 64>>>(out);
    k_post   <<<dim3(16, 8), 256>>>(wp);
    k_redout <<<B_SEG*D_EMB/256, 256>>>(out);
}

// round 3
// speedup vs baseline: 2.2412x; 2.2412x over previous
#include <cuda_runtime.h>
#include <cuda_bf16.h>
#include <math.h>
#include <stdint.h>

#define N_FR   16384
#define D_EMB  1024
#define A_DIM  2048
#define H_H    8
#define B_SEG  64
#define DH     (D_EMB*H_H)
#define NTA    16         // a-tiles of 128
#define PSPL   8          // pool row-splits

// ---------------- scratch ---------------------------------------------------
__device__ __align__(128) __nv_bfloat16 g_xhi[N_FR*D_EMB];
__device__ __align__(128) __nv_bfloat16 g_xlo[N_FR*D_EMB];
__device__ __align__(128) __nv_bfloat16 g_w1hi[A_DIM*D_EMB];   // transposed [A, D]
__device__ __align__(128) __nv_bfloat16 g_w1lo[A_DIM*D_EMB];
__device__ float g_hpart[NTA][N_FR*H_H];
__device__ float g_h[N_FR*H_H];
__device__ float g_attn[N_FR*H_H];
__device__ float g_obdh[B_SEG*DH];
__device__ float g_poolpart[PSPL][B_SEG*DH];
__device__ float g_msumpart[PSPL][B_SEG*D_EMB];
__device__ float g_outpart[8][B_SEG*D_EMB];
__device__ int   g_segstart[B_SEG+1];

// ---------------- helpers ----------------------------------------------------
__device__ __forceinline__ uint32_t smem_u32(const void* p){
    uint32_t a;
    asm("{ .reg .u64 t; cvta.to.shared.u64 t, %1; cvt.u32.u64 %0, t; }" : "=r"(a) : "l"(p));
    return a;
}
__device__ __forceinline__ void cpa16(uint32_t dst, const void* src){
    asm volatile("cp.async.cg.shared.global [%0], [%1], 16;\n" :: "r"(dst), "l"(src));
}
__device__ __forceinline__ void cpa_commit(){ asm volatile("cp.async.commit_group;\n" ::: "memory"); }
__device__ __forceinline__ void cpa_wait1(){ asm volatile("cp.async.wait_group 1;\n" ::: "memory"); }
__device__ __forceinline__ void cpa_wait0(){ asm volatile("cp.async.wait_group 0;\n" ::: "memory"); }

__device__ __forceinline__ void ldm_x4(uint32_t* r, uint32_t addr){
    asm volatile("ldmatrix.sync.aligned.m8n8.x4.shared.b16 {%0,%1,%2,%3}, [%4];"
        : "=r"(r[0]),"=r"(r[1]),"=r"(r[2]),"=r"(r[3]) : "r"(addr));
}
__device__ __forceinline__ void ldm_x2(uint32_t* r, uint32_t addr){
    asm volatile("ldmatrix.sync.aligned.m8n8.x2.shared.b16 {%0,%1}, [%2];"
        : "=r"(r[0]),"=r"(r[1]) : "r"(addr));
}
__device__ __forceinline__ void mma_bf16(float* d, const uint32_t* a, const uint32_t* b){
    asm volatile("mma.sync.aligned.m16n8k16.row.col.f32.bf16.bf16.f32 "
        "{%0,%1,%2,%3}, {%4,%5,%6,%7}, {%8,%9}, {%0,%1,%2,%3};"
        : "+f"(d[0]),"+f"(d[1]),"+f"(d[2]),"+f"(d[3])
        : "r"(a[0]),"r"(a[1]),"r"(a[2]),"r"(a[3]), "r"(b[0]),"r"(b[1]));
}

// ---------------- 0: prefix sum ---------------------------------------------
__global__ void k_prefix(const int* __restrict__ seg){
    if (threadIdx.x == 0){
        int acc = 0; g_segstart[0] = 0;
        for (int i = 0; i < B_SEG; i++){ acc += seg[i]; g_segstart[i+1] = acc; }
    }
}

// ---------------- 1a: split x into bf16 hi/lo ---------------------------------
__global__ __launch_bounds__(256) void k_splitx(const float* __restrict__ x){
    size_t i = ((size_t)blockIdx.x * 256 + threadIdx.x) * 4;
    float4 v = *(const float4*)(x + i);
    float vv[4] = {v.x, v.y, v.z, v.w};
    __nv_bfloat16 h[4], l[4];
    #pragma unroll
    for (int j = 0; j < 4; j++){
        h[j] = __float2bfloat16(vv[j]);
        l[j] = __float2bfloat16(vv[j] - __bfloat162float(h[j]));
    }
    *(__nv_bfloat162*)&g_xhi[i]   = __nv_bfloat162(h[0], h[1]);
    *(__nv_bfloat162*)&g_xhi[i+2] = __nv_bfloat162(h[2], h[3]);
    *(__nv_bfloat162*)&g_xlo[i]   = __nv_bfloat162(l[0], l[1]);
    *(__nv_bfloat162*)&g_xlo[i+2] = __nv_bfloat162(l[2], l[3]);
}

// ---------------- 1b: transpose + split w1 ------------------------------------
__global__ void k_splitw(const float* __restrict__ w1){
    __shared__ float t[32][33];
    int a0 = blockIdx.x * 32, k0 = blockIdx.y * 32;
    int tx = threadIdx.x, ty = threadIdx.y;   // (32, 8)
    #pragma unroll
    for (int i = 0; i < 4; i++)
        t[ty + i*8][tx] = w1[(size_t)(k0 + ty + i*8) * A_DIM + a0 + tx];
    __syncthreads();
    #pragma unroll
    for (int i = 0; i < 4; i++){
        int al = ty + i*8;
        float v = t[tx][al];
        __nv_bfloat16 h = __float2bfloat16(v);
        g_w1hi[(size_t)(a0 + al) * D_EMB + k0 + tx] = h;
        g_w1lo[(size_t)(a0 + al) * D_EMB + k0 + tx] =
            __float2bfloat16(v - __bfloat162float(h));
    }
}

// ---------------- 2: bf16x3 MMA GEMM + fused relu@w2 epilogue -----------------
// CTA 128m x 128a, 8 warps (2x4), warp tile 64x32, K chunks of 32, dbl-buffered.
#define ROWB   80                 // padded row stride in bytes (40 bf16)
#define ARR_SZ (128*ROWB)         // 10240 B per operand array
#define BUF_SZ (4*ARR_SZ)         // XH|XL|WH|WL = 40960 B
#define OFF_XH 0
#define OFF_XL (1*ARR_SZ)
#define OFF_WH (2*ARR_SZ)
#define OFF_WL (3*ARR_SZ)
#define OFF_C  (2*BUF_SZ)                  // 81920
#define C_LD   136                          // fp32 words per C row (128+8 pad)
#define OFF_W2 (OFF_C + 128*C_LD*4)         // 151552
#define SM_TOT (OFF_W2 + 128*H_H*4)         // 155648

__device__ __forceinline__ void load_chunk(uint32_t sbuf, int c, int m0, int a0){
    const int tid = threadIdx.x;
    const int row = tid >> 1;
    const int q   = (tid & 1) * 2;          // 16B chunk pair: j = q, q+1
    const int k0  = c * 32 + q * 8;
    const uint32_t d = sbuf + row * ROWB + q * 16;
    const size_t xo = (size_t)(m0 + row) * D_EMB + k0;
    const size_t wo = (size_t)(a0 + row) * D_EMB + k0;
    cpa16(d + OFF_XH,      g_xhi  + xo);
    cpa16(d + OFF_XH + 16, g_xhi  + xo + 8);
    cpa16(d + OFF_XL,      g_xlo  + xo);
    cpa16(d + OFF_XL + 16, g_xlo  + xo + 8);
    cpa16(d + OFF_WH,      g_w1hi + wo);
    cpa16(d + OFF_WH + 16, g_w1hi + wo + 8);
    cpa16(d + OFF_WL,      g_w1lo + wo);
    cpa16(d + OFF_WL + 16, g_w1lo + wo + 8);
    cpa_commit();
}

__global__ void __launch_bounds__(256, 1) k_mma1(const float* __restrict__ w2){
    extern __shared__ char smem[];
    const uint32_t sb = smem_u32(smem);
    float* Cs  = (float*)(smem + OFF_C);
    float* W2s = (float*)(smem + OFF_W2);
    const int tid = threadIdx.x;
    const int wid = tid >> 5, lane = tid & 31;
    const int wm = wid >> 2, wn = wid & 3;       // warp grid 2x4
    const int grp = lane >> 2, t4 = lane & 3;
    const int m0 = blockIdx.x * 128;
    const int a0 = blockIdx.y * 128;

    for (int i = tid; i < 128 * H_H; i += 256)
        W2s[i] = w2[(size_t)(a0 + (i >> 3)) * H_H + (i & 7)];

    float acc[4][4][4];
    #pragma unroll
    for (int mt = 0; mt < 4; mt++)
        #pragma unroll
        for (int nt = 0; nt < 4; nt++)
            #pragma unroll
            for (int j = 0; j < 4; j++) acc[mt][nt][j] = 0.f;

    load_chunk(sb + 0,      0, m0, a0);
    load_chunk(sb + BUF_SZ, 1, m0, a0);

    // ldmatrix lane addressing (within-warp, constant over loop)
    const int a_row = (lane & 15);          // row within 16-row A tile
    const int a_k8  = (lane >> 4) << 3;     // 0 or 8
    const int b_row = (lane & 7);           // row within 8-row B tile
    const int b_k8  = ((lane >> 3) & 1) << 3;

    for (int c = 0; c < 32; c++){
        const int buf = c & 1;
        const uint32_t base = sb + buf * BUF_SZ;
        if (c >= 30) cpa_wait0(); else cpa_wait1();
        __syncthreads();

        #pragma unroll
        for (int kk = 0; kk < 2; kk++){
            const uint32_t kby = (kk * 16) * 2;
            uint32_t ah[4][4], al[4][4];
            #pragma unroll
            for (int mt = 0; mt < 4; mt++){
                uint32_t ro = (wm * 64 + mt * 16 + a_row) * ROWB + kby + a_k8 * 2;
                ldm_x4(ah[mt], base + OFF_XH + ro);
                ldm_x4(al[mt], base + OFF_XL + ro);
            }
            uint32_t bh[4][2], bl[4][2];
            #pragma unroll
            for (int nt = 0; nt < 4; nt++){
                uint32_t ro = (wn * 32 + nt * 8 + b_row) * ROWB + kby + b_k8 * 2;
                ldm_x2(bh[nt], base + OFF_WH + ro);
                ldm_x2(bl[nt], base + OFF_WL + ro);
            }
            #pragma unroll
            for (int mt = 0; mt < 4; mt++)
                #pragma unroll
                for (int nt = 0; nt < 4; nt++){
                    mma_bf16(acc[mt][nt], ah[mt], bh[nt]);
                    mma_bf16(acc[mt][nt], ah[mt], bl[nt]);
                    mma_bf16(acc[mt][nt], al[mt], bh[nt]);
                }
        }
        __syncthreads();
        if (c + 2 < 32) load_chunk(sb + buf * BUF_SZ, c + 2, m0, a0);
    }

    // relu(C) -> smem
    #pragma unroll
    for (int mt = 0; mt < 4; mt++)
        #pragma unroll
        for (int nt = 0; nt < 4; nt++){
            const int r0 = wm * 64 + mt * 16 + grp;
            const int c0 = wn * 32 + nt * 8 + t4 * 2;
            Cs[(r0    ) * C_LD + c0    ] = fmaxf(acc[mt][nt][0], 0.f);
            Cs[(r0    ) * C_LD + c0 + 1] = fmaxf(acc[mt][nt][1], 0.f);
            Cs[(r0 + 8) * C_LD + c0    ] = fmaxf(acc[mt][nt][2], 0.f);
            Cs[(r0 + 8) * C_LD + c0 + 1] = fmaxf(acc[mt][nt][3], 0.f);
        }
    __syncthreads();

    // h partial: relu(C)[128x128] @ w2slice[128x8]
    #pragma unroll
    for (int it = 0; it < 4; it++){
        const int idx = tid + it * 256;
        const int row = idx >> 3, h = idx & 7;
        float s = 0.f;
        #pragma unroll 8
        for (int cc = 0; cc < 128; cc++)
            s = fmaf(Cs[row * C_LD + cc], W2s[cc * H_H + h], s);
        g_hpart[blockIdx.y][(size_t)(m0 + row) * H_H + h] = s;
    }
}

// ---------------- 3: per-segment softmax (combines 16 partials) ---------------
__global__ __launch_bounds__(256) void k_softmax(){
    const int b = blockIdx.x, tid = threadIdx.x;
    const int start = g_segstart[b];
    const int len = g_segstart[b+1] - start;
    __shared__ float red[256 * H_H];
    __shared__ float mval[H_H], sval[H_H];

    float lm[H_H];
    #pragma unroll
    for (int h = 0; h < H_H; h++) lm[h] = -1e30f;
    for (int r = tid; r < len; r += 256){
        const int n = start + r;
        #pragma unroll
        for (int h = 0; h < H_H; h++){
            float v = 0.f;
            #pragma unroll
            for (int p = 0; p < NTA; p++) v += g_hpart[p][(size_t)n*H_H + h];
            g_h[(size_t)n*H_H + h] = v;
            lm[h] = fmaxf(lm[h], v);
        }
    }
    #pragma unroll
    for (int h = 0; h < H_H; h++) red[tid*H_H + h] = lm[h];
    __syncthreads();
    for (int off = 128; off > 0; off >>= 1){
        if (tid < off)
            #pragma unroll
            for (int h = 0; h < H_H; h++)
                red[tid*H_H+h] = fmaxf(red[tid*H_H+h], red[(tid+off)*H_H+h]);
        __syncthreads();
    }
    if (tid < H_H) mval[tid] = red[tid];
    __syncthreads();

    float ls[H_H];
    #pragma unroll
    for (int h = 0; h < H_H; h++) ls[h] = 0.f;
    for (int r = tid; r < len; r += 256){
        const int n = start + r;
        #pragma unroll
        for (int h = 0; h < H_H; h++) ls[h] += expf(g_h[(size_t)n*H_H+h] - mval[h]);
    }
    #pragma unroll
    for (int h = 0; h < H_H; h++) red[tid*H_H + h] = ls[h];
    __syncthreads();
    for (int off = 128; off > 0; off >>= 1){
        if (tid < off)
            #pragma unroll
            for (int h = 0; h < H_H; h++)
                red[tid*H_H+h] += red[(tid+off)*H_H+h];
        __syncthreads();
    }
    if (tid < H_H) sval[tid] = red[tid];
    __syncthreads();

    float inv[H_H];
    #pragma unroll
    for (int h = 0; h < H_H; h++) inv[h] = 1.f / sval[h];
    for (int r = tid; r < len; r += 256){
        const int n = start + r;
        #pragma unroll
        for (int h = 0; h < H_H; h++)
            g_attn[(size_t)n*H_H+h] = expf(g_h[(size_t)n*H_H+h] - mval[h]) * inv[h];
    }
}

// ---------------- 4: pooling split over rows -----------------------------------
__global__ __launch_bounds__(256) void k_pool(const float* __restrict__ x){
    const int b = blockIdx.x;
    const int d = blockIdx.y * 256 + threadIdx.x;
    const int chunk = blockIdx.z;
    const int start = g_segstart[b];
    const int len = g_segstart[b+1] - start;
    const int cl = (len + PSPL - 1) / PSPL;
    const int r0b = chunk * cl;
    const int r1b = min(len, r0b + cl);

    __shared__ float sat[32][H_H];
    float acc[H_H];
    #pragma unroll
    for (int h = 0; h < H_H; h++) acc[h] = 0.f;
    float ssum = 0.f;

    for (int r0 = r0b; r0 < r1b; r0 += 32){
        const int cnt = min(32, r1b - r0);
        if (threadIdx.x < cnt * H_H){
            const int rr = threadIdx.x >> 3, hh = threadIdx.x & 7;
            sat[rr][hh] = g_attn[(size_t)(start + r0 + rr) * H_H + hh];
        }
        __syncthreads();
        for (int rr = 0; rr < cnt; rr++){
            const float xv = x[(size_t)(start + r0 + rr) * D_EMB + d];
            ssum += xv;
            #pragma unroll
            for (int h = 0; h < H_H; h++) acc[h] = fmaf(xv, sat[rr][h], acc[h]);
        }
        __syncthreads();
    }
    #pragma unroll
    for (int h = 0; h < H_H; h++)
        g_poolpart[chunk][(size_t)b * DH + d * H_H + h] = acc[h];
    g_msumpart[chunk][(size_t)b * D_EMB + d] = ssum;
}

__global__ __launch_bounds__(256) void k_poolred(float* __restrict__ out){
    const int i = blockIdx.x * 256 + threadIdx.x;   // 65536
    const int b = i >> 10, d = i & 1023;
    float acc[H_H];
    #pragma unroll
    for (int h = 0; h < H_H; h++) acc[h] = 0.f;
    float s = 0.f;
    #pragma unroll
    for (int p = 0; p < PSPL; p++){
        #pragma unroll
        for (int h = 0; h < H_H; h++)
            acc[h] += g_poolpart[p][(size_t)b * DH + d * H_H + h];
        s += g_msumpart[p][(size_t)b * D_EMB + d];
    }
    #pragma unroll
    for (int h = 0; h < H_H; h++)
        g_obdh[(size_t)b * DH + d * H_H + h] = acc[h];
    const int len = g_segstart[b+1] - g_segstart[b];
    out[B_SEG * D_EMB + i] = s / (float)len;
}

// ---------------- 5: attn gram --------------------------------------------------
__global__ void k_gram(float* __restrict__ out){
    const int b = blockIdx.x, tid = threadIdx.x;   // 64
    const int i = tid >> 3, j = tid & 7;
    const int start = g_segstart[b];
    const int len = g_segstart[b+1] - start;
    float acc = 0.f;
    for (int r = 0; r < len; r++){
        const float* a = &g_attn[(size_t)(start + r) * H_H];
        acc = fmaf(a[i], a[j], acc);
    }
    out[2 * B_SEG * D_EMB + b * 64 + tid] = acc;
}

// ---------------- 6: post GEMM (64x1024x8192) -----------------------------------
__global__ __launch_bounds__(256) void k_post(const float* __restrict__ wp){
    __shared__ float As[16][72];
    __shared__ float Ws[16][72];
    const int tid = threadIdx.x;
    const int tx = tid & 15, ty = tid >> 4;
    const int j0 = blockIdx.x * 64;
    const int ks = blockIdx.y;
    const int kbase = ks * 1024;

    float acc[4][4];
    #pragma unroll
    for (int i = 0; i < 4; i++)
        #pragma unroll
        for (int j = 0; j < 4; j++) acc[i][j] = 0.f;

    for (int kc = 0; kc < 64; kc++){
        const int k0 = kbase + kc * 16;
        {
            const int row = tid >> 2, q = tid & 3;
            float4 v = *(const float4*)&g_obdh[(size_t)row * DH + k0 + q * 4];
            As[q*4+0][row] = v.x; As[q*4+1][row] = v.y;
            As[q*4+2][row] = v.z; As[q*4+3][row] = v.w;
        }
        {
            const int row = tid >> 4, q = tid & 15;
            float4 v = *(const float4*)&wp[(size_t)(k0 + row) * D_EMB + j0 + q * 4];
            *(float4*)&Ws[row][q * 4] = v;
        }
        __syncthreads();
        #pragma unroll
        for (int k = 0; k < 16; k++){
            float4 av = *(const float4*)&As[k][ty * 4];
            float4 wv = *(const float4*)&Ws[k][tx * 4];
            float ar[4] = {av.x, av.y, av.z, av.w};
            float wr[4] = {wv.x, wv.y, wv.z, wv.w};
            #pragma unroll
            for (int i = 0; i < 4; i++)
                #pragma unroll
                for (int j = 0; j < 4; j++)
                    acc[i][j] = fmaf(ar[i], wr[j], acc[i][j]);
        }
        __syncthreads();
    }
    #pragma unroll
    for (int i = 0; i < 4; i++)
        #pragma unroll
        for (int j = 0; j < 4; j++)
            g_outpart[ks][(size_t)(ty*4 + i) * D_EMB + j0 + tx*4 + j] = acc[i][j];
}

__global__ void k_redout(float* __restrict__ out){
    const int i = blockIdx.x * 256 + threadIdx.x;
    float s = 0.f;
    #pragma unroll
    for (int p = 0; p < 8; p++) s += g_outpart[p][i];
    out[i] = s;
}

// ---------------- launch ----------------------------------------------------------
extern "C" void kernel_launch(void* const* d_in, const int* in_sizes, int n_in,
                              void* d_out, int out_size)
{
    const float* x   = (const float*)d_in[0];
    const int*   seg = (const int*)  d_in[1];
    const float* w1  = (const float*)d_in[2];
    const float* w2  = (const float*)d_in[3];
    const float* wp  = (const float*)d_in[4];
    float* out = (float*)d_out;

    cudaFuncSetAttribute(k_mma1, cudaFuncAttributeMaxDynamicSharedMemorySize, SM_TOT);

    k_prefix  <<<1, 32>>>(seg);
    k_splitx  <<<N_FR*D_EMB/1024, 256>>>(x);
    k_splitw  <<<dim3(A_DIM/32, D_EMB/32), dim3(32, 8)>>>(w1);
    k_mma1    <<<dim3(N_FR/128, NTA), 256, SM_TOT>>>(w2);
    k_softmax <<<B_SEG, 256>>>();
    k_pool    <<<dim3(B_SEG, 4, PSPL), 256>>>(x);
    k_poolred <<<B_SEG*D_EMB/256, 256>>>(out);
    k_gram    <<<B_SEG, 64>>>(out);
    k_post    <<<dim3(16, 8), 256>>>(wp);
    k_redout  <<<B_SEG*D_EMB/256, 256>>>(out);
}

// round 4
// speedup vs baseline: 2.5981x; 1.1592x over previous
#include <cuda_runtime.h>
#include <cuda_bf16.h>
#include <math.h>
#include <stdint.h>

#define N_FR   16384
#define D_EMB  1024
#define A_DIM  2048
#define H_H    8
#define B_SEG  64
#define DH     (D_EMB*H_H)
#define NTA    16         // a-tiles of 128
#define PSPL   8          // pool row-splits

// ---------------- scratch ---------------------------------------------------
__device__ __align__(128) __nv_bfloat16 g_xhi[N_FR*D_EMB];
__device__ __align__(128) __nv_bfloat16 g_xlo[N_FR*D_EMB];
__device__ __align__(128) __nv_bfloat16 g_w1hi[A_DIM*D_EMB];   // transposed [A, D]
__device__ __align__(128) __nv_bfloat16 g_w1lo[A_DIM*D_EMB];
__device__ float g_hpart[NTA][N_FR*H_H];
__device__ float g_h[N_FR*H_H];
__device__ float g_attn[N_FR*H_H];
__device__ float g_obdh[B_SEG*DH];
__device__ float g_poolpart[PSPL][B_SEG*DH];
__device__ float g_msumpart[PSPL][B_SEG*D_EMB];
__device__ float g_outpart[8][B_SEG*D_EMB];
__device__ int   g_segstart[B_SEG+1];

// ---------------- helpers ----------------------------------------------------
__device__ __forceinline__ uint32_t smem_u32(const void* p){
    uint32_t a;
    asm("{ .reg .u64 t; cvta.to.shared.u64 t, %1; cvt.u32.u64 %0, t; }" : "=r"(a) : "l"(p));
    return a;
}
__device__ __forceinline__ void cpa16(uint32_t dst, const void* src){
    asm volatile("cp.async.cg.shared.global [%0], [%1], 16;\n" :: "r"(dst), "l"(src));
}
__device__ __forceinline__ void cpa_commit(){ asm volatile("cp.async.commit_group;\n" ::: "memory"); }
__device__ __forceinline__ void cpa_wait1(){ asm volatile("cp.async.wait_group 1;\n" ::: "memory"); }
__device__ __forceinline__ void cpa_wait0(){ asm volatile("cp.async.wait_group 0;\n" ::: "memory"); }

__device__ __forceinline__ void ldm_x4(uint32_t* r, uint32_t addr){
    asm volatile("ldmatrix.sync.aligned.m8n8.x4.shared.b16 {%0,%1,%2,%3}, [%4];"
        : "=r"(r[0]),"=r"(r[1]),"=r"(r[2]),"=r"(r[3]) : "r"(addr));
}
__device__ __forceinline__ void ldm_x2(uint32_t* r, uint32_t addr){
    asm volatile("ldmatrix.sync.aligned.m8n8.x2.shared.b16 {%0,%1}, [%2];"
        : "=r"(r[0]),"=r"(r[1]) : "r"(addr));
}
__device__ __forceinline__ void mma_bf16(float* d, const uint32_t* a, const uint32_t* b){
    asm volatile("mma.sync.aligned.m16n8k16.row.col.f32.bf16.bf16.f32 "
        "{%0,%1,%2,%3}, {%4,%5,%6,%7}, {%8,%9}, {%0,%1,%2,%3};"
        : "+f"(d[0]),"+f"(d[1]),"+f"(d[2]),"+f"(d[3])
        : "r"(a[0]),"r"(a[1]),"r"(a[2]),"r"(a[3]), "r"(b[0]),"r"(b[1]));
}

// ---------------- 0: prefix sum ---------------------------------------------
__global__ void k_prefix(const int* __restrict__ seg){
    if (threadIdx.x == 0){
        int acc = 0; g_segstart[0] = 0;
        for (int i = 0; i < B_SEG; i++){ acc += seg[i]; g_segstart[i+1] = acc; }
    }
}

// ---------------- 1a: split x into bf16 hi/lo ---------------------------------
__global__ __launch_bounds__(256) void k_splitx(const float* __restrict__ x){
    size_t i = ((size_t)blockIdx.x * 256 + threadIdx.x) * 4;
    float4 v = *(const float4*)(x + i);
    float vv[4] = {v.x, v.y, v.z, v.w};
    __nv_bfloat16 h[4], l[4];
    #pragma unroll
    for (int j = 0; j < 4; j++){
        h[j] = __float2bfloat16(vv[j]);
        l[j] = __float2bfloat16(vv[j] - __bfloat162float(h[j]));
    }
    *(__nv_bfloat162*)&g_xhi[i]   = __nv_bfloat162(h[0], h[1]);
    *(__nv_bfloat162*)&g_xhi[i+2] = __nv_bfloat162(h[2], h[3]);
    *(__nv_bfloat162*)&g_xlo[i]   = __nv_bfloat162(l[0], l[1]);
    *(__nv_bfloat162*)&g_xlo[i+2] = __nv_bfloat162(l[2], l[3]);
}

// ---------------- 1b: transpose + split w1 ------------------------------------
__global__ void k_splitw(const float* __restrict__ w1){
    __shared__ float t[32][33];
    int a0 = blockIdx.x * 32, k0 = blockIdx.y * 32;
    int tx = threadIdx.x, ty = threadIdx.y;   // (32, 8)
    #pragma unroll
    for (int i = 0; i < 4; i++)
        t[ty + i*8][tx] = w1[(size_t)(k0 + ty + i*8) * A_DIM + a0 + tx];
    __syncthreads();
    #pragma unroll
    for (int i = 0; i < 4; i++){
        int al = ty + i*8;
        float v = t[tx][al];
        __nv_bfloat16 h = __float2bfloat16(v);
        g_w1hi[(size_t)(a0 + al) * D_EMB + k0 + tx] = h;
        g_w1lo[(size_t)(a0 + al) * D_EMB + k0 + tx] =
            __float2bfloat16(v - __bfloat162float(h));
    }
}

// ---------------- 2: bf16x3 MMA GEMM + fused relu@w2 epilogue -----------------
// CTA 128m x 128a, 8 warps (2x4), warp tile 64x32, K chunks of 32, dbl-buffered.
// C epilogue staging UNIONS with the operand buffers -> 86KB smem -> 2 CTAs/SM.
#define ROWB   80                 // padded row stride in bytes (40 bf16)
#define ARR_SZ (128*ROWB)         // 10240 B per operand array
#define BUF_SZ (4*ARR_SZ)         // XH|XL|WH|WL = 40960 B
#define OFF_XH 0
#define OFF_XL (1*ARR_SZ)
#define OFF_WH (2*ARR_SZ)
#define OFF_WL (3*ARR_SZ)
#define OFF_C  0                            // union with buffers (post-loop only)
#define C_LD   136                          // fp32 words per C row (128+8 pad)
#define OFF_W2 (2*BUF_SZ)                   // 81920
#define SM_TOT (OFF_W2 + 128*H_H*4)         // 86016

__device__ __forceinline__ void load_chunk(uint32_t sbuf, int c, int m0, int a0){
    const int tid = threadIdx.x;
    const int row = tid >> 1;
    const int q   = (tid & 1) * 2;          // 16B chunk pair: j = q, q+1
    const int k0  = c * 32 + q * 8;
    const uint32_t d = sbuf + row * ROWB + q * 16;
    const size_t xo = (size_t)(m0 + row) * D_EMB + k0;
    const size_t wo = (size_t)(a0 + row) * D_EMB + k0;
    cpa16(d + OFF_XH,      g_xhi  + xo);
    cpa16(d + OFF_XH + 16, g_xhi  + xo + 8);
    cpa16(d + OFF_XL,      g_xlo  + xo);
    cpa16(d + OFF_XL + 16, g_xlo  + xo + 8);
    cpa16(d + OFF_WH,      g_w1hi + wo);
    cpa16(d + OFF_WH + 16, g_w1hi + wo + 8);
    cpa16(d + OFF_WL,      g_w1lo + wo);
    cpa16(d + OFF_WL + 16, g_w1lo + wo + 8);
    cpa_commit();
}

__global__ void __launch_bounds__(256, 2) k_mma1(const float* __restrict__ w2){
    extern __shared__ char smem[];
    const uint32_t sb = smem_u32(smem);
    float* Cs  = (float*)(smem + OFF_C);
    float* W2s = (float*)(smem + OFF_W2);
    const int tid = threadIdx.x;
    const int wid = tid >> 5, lane = tid & 31;
    const int wm = wid >> 2, wn = wid & 3;       // warp grid 2x4
    const int grp = lane >> 2, t4 = lane & 3;
    const int m0 = blockIdx.x * 128;
    const int a0 = blockIdx.y * 128;

    for (int i = tid; i < 128 * H_H; i += 256)
        W2s[i] = w2[(size_t)(a0 + (i >> 3)) * H_H + (i & 7)];

    float acc[4][4][4];
    #pragma unroll
    for (int mt = 0; mt < 4; mt++)
        #pragma unroll
        for (int nt = 0; nt < 4; nt++)
            #pragma unroll
            for (int j = 0; j < 4; j++) acc[mt][nt][j] = 0.f;

    load_chunk(sb + 0,      0, m0, a0);
    load_chunk(sb + BUF_SZ, 1, m0, a0);

    // ldmatrix lane addressing (within-warp, constant over loop)
    const int a_row = (lane & 15);          // row within 16-row A tile
    const int a_k8  = (lane >> 4) << 3;     // 0 or 8
    const int b_row = (lane & 7);           // row within 8-row B tile
    const int b_k8  = ((lane >> 3) & 1) << 3;

    for (int c = 0; c < 32; c++){
        const int buf = c & 1;
        const uint32_t base = sb + buf * BUF_SZ;
        if (c >= 30) cpa_wait0(); else cpa_wait1();
        __syncthreads();

        #pragma unroll
        for (int kk = 0; kk < 2; kk++){
            const uint32_t kby = (kk * 16) * 2;
            // hi A frags + hi B frags, hh MMAs
            uint32_t ah[4][4];
            #pragma unroll
            for (int mt = 0; mt < 4; mt++){
                uint32_t ro = (wm * 64 + mt * 16 + a_row) * ROWB + kby + a_k8 * 2;
                ldm_x4(ah[mt], base + OFF_XH + ro);
            }
            uint32_t bh[4][2];
            #pragma unroll
            for (int nt = 0; nt < 4; nt++){
                uint32_t ro = (wn * 32 + nt * 8 + b_row) * ROWB + kby + b_k8 * 2;
                ldm_x2(bh[nt], base + OFF_WH + ro);
            }
            #pragma unroll
            for (int mt = 0; mt < 4; mt++)
                #pragma unroll
                for (int nt = 0; nt < 4; nt++)
                    mma_bf16(acc[mt][nt], ah[mt], bh[nt]);
            // lo B frags, h*l MMAs (ah dies after this)
            {
                uint32_t bl[4][2];
                #pragma unroll
                for (int nt = 0; nt < 4; nt++){
                    uint32_t ro = (wn * 32 + nt * 8 + b_row) * ROWB + kby + b_k8 * 2;
                    ldm_x2(bl[nt], base + OFF_WL + ro);
                }
                #pragma unroll
                for (int mt = 0; mt < 4; mt++)
                    #pragma unroll
                    for (int nt = 0; nt < 4; nt++)
                        mma_bf16(acc[mt][nt], ah[mt], bl[nt]);
            }
            // lo A frags, l*h MMAs
            {
                uint32_t al[4][4];
                #pragma unroll
                for (int mt = 0; mt < 4; mt++){
                    uint32_t ro = (wm * 64 + mt * 16 + a_row) * ROWB + kby + a_k8 * 2;
                    ldm_x4(al[mt], base + OFF_XL + ro);
                }
                #pragma unroll
                for (int mt = 0; mt < 4; mt++)
                    #pragma unroll
                    for (int nt = 0; nt < 4; nt++)
                        mma_bf16(acc[mt][nt], al[mt], bh[nt]);
            }
        }
        __syncthreads();
        if (c + 2 < 32) load_chunk(sb + buf * BUF_SZ, c + 2, m0, a0);
    }
    __syncthreads();   // all warps done reading buffers before C overwrites them

    // relu(C) -> smem (union region)
    #pragma unroll
    for (int mt = 0; mt < 4; mt++)
        #pragma unroll
        for (int nt = 0; nt < 4; nt++){
            const int r0 = wm * 64 + mt * 16 + grp;
            const int c0 = wn * 32 + nt * 8 + t4 * 2;
            Cs[(r0    ) * C_LD + c0    ] = fmaxf(acc[mt][nt][0], 0.f);
            Cs[(r0    ) * C_LD + c0 + 1] = fmaxf(acc[mt][nt][1], 0.f);
            Cs[(r0 + 8) * C_LD + c0    ] = fmaxf(acc[mt][nt][2], 0.f);
            Cs[(r0 + 8) * C_LD + c0 + 1] = fmaxf(acc[mt][nt][3], 0.f);
        }
    __syncthreads();

    // h partial: relu(C)[128x128] @ w2slice[128x8]
    #pragma unroll
    for (int it = 0; it < 4; it++){
        const int idx = tid + it * 256;
        const int row = idx >> 3, h = idx & 7;
        float s = 0.f;
        #pragma unroll 8
        for (int cc = 0; cc < 128; cc++)
            s = fmaf(Cs[row * C_LD + cc], W2s[cc * H_H + h], s);
        g_hpart[blockIdx.y][(size_t)(m0 + row) * H_H + h] = s;
    }
}

// ---------------- 3: per-segment softmax (combines 16 partials) ---------------
__global__ __launch_bounds__(256) void k_softmax(){
    const int b = blockIdx.x, tid = threadIdx.x;
    const int start = g_segstart[b];
    const int len = g_segstart[b+1] - start;
    __shared__ float red[256 * H_H];
    __shared__ float mval[H_H], sval[H_H];

    float lm[H_H];
    #pragma unroll
    for (int h = 0; h < H_H; h++) lm[h] = -1e30f;
    for (int r = tid; r < len; r += 256){
        const int n = start + r;
        #pragma unroll
        for (int h = 0; h < H_H; h++){
            float v = 0.f;
            #pragma unroll
            for (int p = 0; p < NTA; p++) v += g_hpart[p][(size_t)n*H_H + h];
            g_h[(size_t)n*H_H + h] = v;
            lm[h] = fmaxf(lm[h], v);
        }
    }
    #pragma unroll
    for (int h = 0; h < H_H; h++) red[tid*H_H + h] = lm[h];
    __syncthreads();
    for (int off = 128; off > 0; off >>= 1){
        if (tid < off)
            #pragma unroll
            for (int h = 0; h < H_H; h++)
                red[tid*H_H+h] = fmaxf(red[tid*H_H+h], red[(tid+off)*H_H+h]);
        __syncthreads();
    }
    if (tid < H_H) mval[tid] = red[tid];
    __syncthreads();

    float ls[H_H];
    #pragma unroll
    for (int h = 0; h < H_H; h++) ls[h] = 0.f;
    for (int r = tid; r < len; r += 256){
        const int n = start + r;
        #pragma unroll
        for (int h = 0; h < H_H; h++) ls[h] += expf(g_h[(size_t)n*H_H+h] - mval[h]);
    }
    #pragma unroll
    for (int h = 0; h < H_H; h++) red[tid*H_H + h] = ls[h];
    __syncthreads();
    for (int off = 128; off > 0; off >>= 1){
        if (tid < off)
            #pragma unroll
            for (int h = 0; h < H_H; h++)
                red[tid*H_H+h] += red[(tid+off)*H_H+h];
        __syncthreads();
    }
    if (tid < H_H) sval[tid] = red[tid];
    __syncthreads();

    float inv[H_H];
    #pragma unroll
    for (int h = 0; h < H_H; h++) inv[h] = 1.f / sval[h];
    for (int r = tid; r < len; r += 256){
        const int n = start + r;
        #pragma unroll
        for (int h = 0; h < H_H; h++)
            g_attn[(size_t)n*H_H+h] = expf(g_h[(size_t)n*H_H+h] - mval[h]) * inv[h];
    }
}

// ---------------- 4: pooling split over rows -----------------------------------
__global__ __launch_bounds__(256) void k_pool(const float* __restrict__ x){
    const int b = blockIdx.x;
    const int d = blockIdx.y * 256 + threadIdx.x;
    const int chunk = blockIdx.z;
    const int start = g_segstart[b];
    const int len = g_segstart[b+1] - start;
    const int cl = (len + PSPL - 1) / PSPL;
    const int r0b = chunk * cl;
    const int r1b = min(len, r0b + cl);

    __shared__ float sat[32][H_H];
    float acc[H_H];
    #pragma unroll
    for (int h = 0; h < H_H; h++) acc[h] = 0.f;
    float ssum = 0.f;

    for (int r0 = r0b; r0 < r1b; r0 += 32){
        const int cnt = min(32, r1b - r0);
        if (threadIdx.x < cnt * H_H){
            const int rr = threadIdx.x >> 3, hh = threadIdx.x & 7;
            sat[rr][hh] = g_attn[(size_t)(start + r0 + rr) * H_H + hh];
        }
        __syncthreads();
        for (int rr = 0; rr < cnt; rr++){
            const float xv = x[(size_t)(start + r0 + rr) * D_EMB + d];
            ssum += xv;
            #pragma unroll
            for (int h = 0; h < H_H; h++) acc[h] = fmaf(xv, sat[rr][h], acc[h]);
        }
        __syncthreads();
    }
    #pragma unroll
    for (int h = 0; h < H_H; h++)
        g_poolpart[chunk][(size_t)b * DH + d * H_H + h] = acc[h];
    g_msumpart[chunk][(size_t)b * D_EMB + d] = ssum;
}

__global__ __launch_bounds__(256) void k_poolred(float* __restrict__ out){
    const int i = blockIdx.x * 256 + threadIdx.x;   // 65536
    const int b = i >> 10, d = i & 1023;
    float acc[H_H];
    #pragma unroll
    for (int h = 0; h < H_H; h++) acc[h] = 0.f;
    float s = 0.f;
    #pragma unroll
    for (int p = 0; p < PSPL; p++){
        #pragma unroll
        for (int h = 0; h < H_H; h++)
            acc[h] += g_poolpart[p][(size_t)b * DH + d * H_H + h];
        s += g_msumpart[p][(size_t)b * D_EMB + d];
    }
    #pragma unroll
    for (int h = 0; h < H_H; h++)
        g_obdh[(size_t)b * DH + d * H_H + h] = acc[h];
    const int len = g_segstart[b+1] - g_segstart[b];
    out[B_SEG * D_EMB + i] = s / (float)len;
}

// ---------------- 5: attn gram --------------------------------------------------
__global__ void k_gram(float* __restrict__ out){
    const int b = blockIdx.x, tid = threadIdx.x;   // 64
    const int i = tid >> 3, j = tid & 7;
    const int start = g_segstart[b];
    const int len = g_segstart[b+1] - start;
    float acc = 0.f;
    for (int r = 0; r < len; r++){
        const float* a = &g_attn[(size_t)(start + r) * H_H];
        acc = fmaf(a[i], a[j], acc);
    }
    out[2 * B_SEG * D_EMB + b * 64 + tid] = acc;
}

// ---------------- 6: post GEMM (64x1024x8192) -----------------------------------
__global__ __launch_bounds__(256) void k_post(const float* __restrict__ wp){
    __shared__ float As[16][72];
    __shared__ float Ws[16][72];
    const int tid = threadIdx.x;
    const int tx = tid & 15, ty = tid >> 4;
    const int j0 = blockIdx.x * 64;
    const int ks = blockIdx.y;
    const int kbase = ks * 1024;

    float acc[4][4];
    #pragma unroll
    for (int i = 0; i < 4; i++)
        #pragma unroll
        for (int j = 0; j < 4; j++) acc[i][j] = 0.f;

    for (int kc = 0; kc < 64; kc++){
        const int k0 = kbase + kc * 16;
        {
            const int row = tid >> 2, q = tid & 3;
            float4 v = *(const float4*)&g_obdh[(size_t)row * DH + k0 + q * 4];
            As[q*4+0][row] = v.x; As[q*4+1][row] = v.y;
            As[q*4+2][row] = v.z; As[q*4+3][row] = v.w;
        }
        {
            const int row = tid >> 4, q = tid & 15;
            float4 v = *(const float4*)&wp[(size_t)(k0 + row) * D_EMB + j0 + q * 4];
            *(float4*)&Ws[row][q * 4] = v;
        }
        __syncthreads();
        #pragma unroll
        for (int k = 0; k < 16; k++){
            float4 av = *(const float4*)&As[k][ty * 4];
            float4 wv = *(const float4*)&Ws[k][tx * 4];
            float ar[4] = {av.x, av.y, av.z, av.w};
            float wr[4] = {wv.x, wv.y, wv.z, wv.w};
            #pragma unroll
            for (int i = 0; i < 4; i++)
                #pragma unroll
                for (int j = 0; j < 4; j++)
                    acc[i][j] = fmaf(ar[i], wr[j], acc[i][j]);
        }
        __syncthreads();
    }
    #pragma unroll
    for (int i = 0; i < 4; i++)
        #pragma unroll
        for (int j = 0; j < 4; j++)
            g_outpart[ks][(size_t)(ty*4 + i) * D_EMB + j0 + tx*4 + j] = acc[i][j];
}

__global__ void k_redout(float* __restrict__ out){
    const int i = blockIdx.x * 256 + threadIdx.x;
    float s = 0.f;
    #pragma unroll
    for (int p = 0; p < 8; p++) s += g_outpart[p][i];
    out[i] = s;
}

// ---------------- launch ----------------------------------------------------------
extern "C" void kernel_launch(void* const* d_in, const int* in_sizes, int n_in,
                              void* d_out, int out_size)
{
    const float* x   = (const float*)d_in[0];
    const int*   seg = (const int*)  d_in[1];
    const float* w1  = (const float*)d_in[2];
    const float* w2  = (const float*)d_in[3];
    const float* wp  = (const float*)d_in[4];
    float* out = (float*)d_out;

    cudaFuncSetAttribute(k_mma1, cudaFuncAttributeMaxDynamicSharedMemorySize, SM_TOT);

    k_prefix  <<<1, 32>>>(seg);
    k_splitx  <<<N_FR*D_EMB/1024, 256>>>(x);
    k_splitw  <<<dim3(A_DIM/32, D_EMB/32), dim3(32, 8)>>>(w1);
    k_mma1    <<<dim3(N_FR/128, NTA), 256, SM_TOT>>>(w2);
    k_softmax <<<B_SEG, 256>>>();
    k_pool    <<<dim3(B_SEG, 4, PSPL), 256>>>(x);
    k_poolred <<<B_SEG*D_EMB/256, 256>>>(out);
    k_gram    <<<B_SEG, 64>>>(out);
    k_post    <<<dim3(16, 8), 256>>>(wp);
    k_redout  <<<B_SEG*D_EMB/256, 256>>>(out);
}

// round 5
// speedup vs baseline: 2.6445x; 1.0178x over previous
#include <cuda_runtime.h>
#include <cuda_bf16.h>
#include <math.h>
#include <stdint.h>

#define N_FR   16384
#define D_EMB  1024
#define A_DIM  2048
#define H_H    8
#define B_SEG  64
#define DH     (D_EMB*H_H)
#define NTA    16         // a-tiles of 128
#define PSPL   8          // pool row-splits

// ---------------- scratch ---------------------------------------------------
__device__ __align__(128) __nv_bfloat16 g_xhi[N_FR*D_EMB];
__device__ __align__(128) __nv_bfloat16 g_xlo[N_FR*D_EMB];
__device__ __align__(128) __nv_bfloat16 g_w1hi[A_DIM*D_EMB];   // transposed [A, D]
__device__ __align__(128) __nv_bfloat16 g_w1lo[A_DIM*D_EMB];
__device__ float g_hpart[NTA][N_FR*H_H];
__device__ float g_h[N_FR*H_H];
__device__ float g_attn[N_FR*H_H];
__device__ float g_obdh[B_SEG*DH];
__device__ float g_poolpart[PSPL][B_SEG*DH];
__device__ float g_msumpart[PSPL][B_SEG*D_EMB];
__device__ float g_outpart[8][B_SEG*D_EMB];
__device__ int   g_segstart[B_SEG+1];

// ---------------- helpers ----------------------------------------------------
__device__ __forceinline__ uint32_t smem_u32(const void* p){
    uint32_t a;
    asm("{ .reg .u64 t; cvta.to.shared.u64 t, %1; cvt.u32.u64 %0, t; }" : "=r"(a) : "l"(p));
    return a;
}
__device__ __forceinline__ void cpa16(uint32_t dst, const void* src){
    asm volatile("cp.async.cg.shared.global [%0], [%1], 16;\n" :: "r"(dst), "l"(src));
}
__device__ __forceinline__ void cpa_commit(){ asm volatile("cp.async.commit_group;\n" ::: "memory"); }
__device__ __forceinline__ void cpa_wait1(){ asm volatile("cp.async.wait_group 1;\n" ::: "memory"); }
__device__ __forceinline__ void cpa_wait0(){ asm volatile("cp.async.wait_group 0;\n" ::: "memory"); }

__device__ __forceinline__ void ldm_x4(uint32_t* r, uint32_t addr){
    asm volatile("ldmatrix.sync.aligned.m8n8.x4.shared.b16 {%0,%1,%2,%3}, [%4];"
        : "=r"(r[0]),"=r"(r[1]),"=r"(r[2]),"=r"(r[3]) : "r"(addr));
}
__device__ __forceinline__ void ldm_x2(uint32_t* r, uint32_t addr){
    asm volatile("ldmatrix.sync.aligned.m8n8.x2.shared.b16 {%0,%1}, [%2];"
        : "=r"(r[0]),"=r"(r[1]) : "r"(addr));
}
__device__ __forceinline__ void mma_bf16(float* d, const uint32_t* a, const uint32_t* b){
    asm volatile("mma.sync.aligned.m16n8k16.row.col.f32.bf16.bf16.f32 "
        "{%0,%1,%2,%3}, {%4,%5,%6,%7}, {%8,%9}, {%0,%1,%2,%3};"
        : "+f"(d[0]),"+f"(d[1]),"+f"(d[2]),"+f"(d[3])
        : "r"(a[0]),"r"(a[1]),"r"(a[2]),"r"(a[3]), "r"(b[0]),"r"(b[1]));
}

// ---------------- 0: prefix sum ---------------------------------------------
__global__ void k_prefix(const int* __restrict__ seg){
    if (threadIdx.x == 0){
        int acc = 0; g_segstart[0] = 0;
        for (int i = 0; i < B_SEG; i++){ acc += seg[i]; g_segstart[i+1] = acc; }
    }
}

// ---------------- 1a: split x into bf16 hi/lo ---------------------------------
__global__ __launch_bounds__(256) void k_splitx(const float* __restrict__ x){
    size_t i = ((size_t)blockIdx.x * 256 + threadIdx.x) * 4;
    float4 v = *(const float4*)(x + i);
    float vv[4] = {v.x, v.y, v.z, v.w};
    __nv_bfloat16 h[4], l[4];
    #pragma unroll
    for (int j = 0; j < 4; j++){
        h[j] = __float2bfloat16(vv[j]);
        l[j] = __float2bfloat16(vv[j] - __bfloat162float(h[j]));
    }
    *(__nv_bfloat162*)&g_xhi[i]   = __nv_bfloat162(h[0], h[1]);
    *(__nv_bfloat162*)&g_xhi[i+2] = __nv_bfloat162(h[2], h[3]);
    *(__nv_bfloat162*)&g_xlo[i]   = __nv_bfloat162(l[0], l[1]);
    *(__nv_bfloat162*)&g_xlo[i+2] = __nv_bfloat162(l[2], l[3]);
}

// ---------------- 1b: transpose + split w1 ------------------------------------
__global__ void k_splitw(const float* __restrict__ w1){
    __shared__ float t[32][33];
    int a0 = blockIdx.x * 32, k0 = blockIdx.y * 32;
    int tx = threadIdx.x, ty = threadIdx.y;   // (32, 8)
    #pragma unroll
    for (int i = 0; i < 4; i++)
        t[ty + i*8][tx] = w1[(size_t)(k0 + ty + i*8) * A_DIM + a0 + tx];
    __syncthreads();
    #pragma unroll
    for (int i = 0; i < 4; i++){
        int al = ty + i*8;
        float v = t[tx][al];
        __nv_bfloat16 h = __float2bfloat16(v);
        g_w1hi[(size_t)(a0 + al) * D_EMB + k0 + tx] = h;
        g_w1lo[(size_t)(a0 + al) * D_EMB + k0 + tx] =
            __float2bfloat16(v - __bfloat162float(h));
    }
}

// ---------------- 2: bf16x3 MMA GEMM + fused relu@w2 epilogue -----------------
// CTA 128m x 128a, 8 warps (2x4), warp tile 64x32, K chunks of 32.
// 64B rows with XOR-4 swizzle (conflict-free ldmatrix, no padding).
// 3-stage cp.async pipeline -> single __syncthreads per chunk. 2 CTAs/SM.
#define ROWB   64                 // row stride in bytes (32 bf16, swizzled)
#define ARR_SZ (128*ROWB)         // 8192 B per operand array
#define STG_SZ (4*ARR_SZ)         // XH|XL|WH|WL = 32768 B
#define OFF_XH 0
#define OFF_XL (1*ARR_SZ)
#define OFF_WH (2*ARR_SZ)
#define OFF_WL (3*ARR_SZ)
#define OFF_C  0                            // union with stage buffers
#define C_LD   136                          // fp32 words per C row (128+8 pad)
#define OFF_W2 (3*STG_SZ)                   // 98304
#define SM_TOT (OFF_W2 + 128*H_H*4)         // 102400

// swizzled byte offset of (row, 16B-chunk j) within one operand array
__device__ __forceinline__ uint32_t swz(int row, int j){
    return (uint32_t)(row * ROWB + ((j ^ (row & 3)) << 4));
}

__device__ __forceinline__ void load_chunk(uint32_t sbuf, int c, int m0, int a0){
    const int tid = threadIdx.x;
    const int row = tid >> 1;
    const int j0  = (tid & 1) * 2;          // 16B chunks j0, j0+1
    const size_t xo = (size_t)(m0 + row) * D_EMB + c * 32;
    const size_t wo = (size_t)(a0 + row) * D_EMB + c * 32;
    #pragma unroll
    for (int j = j0; j < j0 + 2; j++){
        const uint32_t so = swz(row, j);
        cpa16(sbuf + OFF_XH + so, g_xhi  + xo + j * 8);
        cpa16(sbuf + OFF_XL + so, g_xlo  + xo + j * 8);
        cpa16(sbuf + OFF_WH + so, g_w1hi + wo + j * 8);
        cpa16(sbuf + OFF_WL + so, g_w1lo + wo + j * 8);
    }
    cpa_commit();
}

__global__ void __launch_bounds__(256, 2) k_mma1(const float* __restrict__ w2){
    extern __shared__ char smem[];
    const uint32_t sb = smem_u32(smem);
    float* Cs  = (float*)(smem + OFF_C);
    float* W2s = (float*)(smem + OFF_W2);
    const int tid = threadIdx.x;
    const int wid = tid >> 5, lane = tid & 31;
    const int wm = wid >> 2, wn = wid & 3;       // warp grid 2x4
    const int grp = lane >> 2, t4 = lane & 3;
    const int m0 = blockIdx.x * 128;
    const int a0 = blockIdx.y * 128;

    for (int i = tid; i < 128 * H_H; i += 256)
        W2s[i] = w2[(size_t)(a0 + (i >> 3)) * H_H + (i & 7)];

    float acc[4][4][4];
    #pragma unroll
    for (int mt = 0; mt < 4; mt++)
        #pragma unroll
        for (int nt = 0; nt < 4; nt++)
            #pragma unroll
            for (int j = 0; j < 4; j++) acc[mt][nt][j] = 0.f;

    load_chunk(sb + 0*STG_SZ, 0, m0, a0);
    load_chunk(sb + 1*STG_SZ, 1, m0, a0);

    // ldmatrix lane addressing constants
    const int a_row = (lane & 15);          // row within 16-row A tile
    const int a_jh  = (lane >> 4);          // 16B-chunk half select (0/1)
    const int b_row = (lane & 7);
    const int b_jh  = ((lane >> 3) & 1);

    uint32_t base = sb;                     // stage 0
    for (int c = 0; c < 32; c++){
        if (c == 31) cpa_wait0(); else cpa_wait1();
        __syncthreads();
        if (c + 2 < 32)
            load_chunk(sb + ((c + 2) % 3) * STG_SZ, c + 2, m0, a0);

        #pragma unroll
        for (int kk = 0; kk < 2; kk++){
            const int jb = kk * 2;          // first 16B chunk of this k16
            // hi A + hi B, hh MMAs
            uint32_t ah[4][4];
            #pragma unroll
            for (int mt = 0; mt < 4; mt++){
                int r = wm * 64 + mt * 16 + a_row;
                ldm_x4(ah[mt], base + OFF_XH + swz(r, jb + a_jh));
            }
            uint32_t bh[4][2];
            #pragma unroll
            for (int nt = 0; nt < 4; nt++){
                int r = wn * 32 + nt * 8 + b_row;
                ldm_x2(bh[nt], base + OFF_WH + swz(r, jb + b_jh));
            }
            #pragma unroll
            for (int mt = 0; mt < 4; mt++)
                #pragma unroll
                for (int nt = 0; nt < 4; nt++)
                    mma_bf16(acc[mt][nt], ah[mt], bh[nt]);
            // lo B, h*l MMAs
            {
                uint32_t bl[4][2];
                #pragma unroll
                for (int nt = 0; nt < 4; nt++){
                    int r = wn * 32 + nt * 8 + b_row;
                    ldm_x2(bl[nt], base + OFF_WL + swz(r, jb + b_jh));
                }
                #pragma unroll
                for (int mt = 0; mt < 4; mt++)
                    #pragma unroll
                    for (int nt = 0; nt < 4; nt++)
                        mma_bf16(acc[mt][nt], ah[mt], bl[nt]);
            }
            // lo A, l*h MMAs
            {
                uint32_t al[4][4];
                #pragma unroll
                for (int mt = 0; mt < 4; mt++){
                    int r = wm * 64 + mt * 16 + a_row;
                    ldm_x4(al[mt], base + OFF_XL + swz(r, jb + a_jh));
                }
                #pragma unroll
                for (int mt = 0; mt < 4; mt++)
                    #pragma unroll
                    for (int nt = 0; nt < 4; nt++)
                        mma_bf16(acc[mt][nt], al[mt], bh[nt]);
            }
        }
        base = sb + ((c + 1) % 3) * STG_SZ;
    }
    __syncthreads();   // all warps done reading buffers before C overwrites them

    // relu(C) -> smem (union region)
    #pragma unroll
    for (int mt = 0; mt < 4; mt++)
        #pragma unroll
        for (int nt = 0; nt < 4; nt++){
            const int r0 = wm * 64 + mt * 16 + grp;
            const int c0 = wn * 32 + nt * 8 + t4 * 2;
            Cs[(r0    ) * C_LD + c0    ] = fmaxf(acc[mt][nt][0], 0.f);
            Cs[(r0    ) * C_LD + c0 + 1] = fmaxf(acc[mt][nt][1], 0.f);
            Cs[(r0 + 8) * C_LD + c0    ] = fmaxf(acc[mt][nt][2], 0.f);
            Cs[(r0 + 8) * C_LD + c0 + 1] = fmaxf(acc[mt][nt][3], 0.f);
        }
    __syncthreads();

    // h partial: relu(C)[128x128] @ w2slice[128x8]
    #pragma unroll
    for (int it = 0; it < 4; it++){
        const int idx = tid + it * 256;
        const int row = idx >> 3, h = idx & 7;
        float s = 0.f;
        #pragma unroll 8
        for (int cc = 0; cc < 128; cc++)
            s = fmaf(Cs[row * C_LD + cc], W2s[cc * H_H + h], s);
        g_hpart[blockIdx.y][(size_t)(m0 + row) * H_H + h] = s;
    }
}

// ---------------- 3: per-segment softmax (combines 16 partials) ---------------
__global__ __launch_bounds__(256) void k_softmax(){
    const int b = blockIdx.x, tid = threadIdx.x;
    const int start = g_segstart[b];
    const int len = g_segstart[b+1] - start;
    __shared__ float red[256 * H_H];
    __shared__ float mval[H_H], sval[H_H];

    float lm[H_H];
    #pragma unroll
    for (int h = 0; h < H_H; h++) lm[h] = -1e30f;
    for (int r = tid; r < len; r += 256){
        const int n = start + r;
        #pragma unroll
        for (int h = 0; h < H_H; h++){
            float v = 0.f;
            #pragma unroll
            for (int p = 0; p < NTA; p++) v += g_hpart[p][(size_t)n*H_H + h];
            g_h[(size_t)n*H_H + h] = v;
            lm[h] = fmaxf(lm[h], v);
        }
    }
    #pragma unroll
    for (int h = 0; h < H_H; h++) red[tid*H_H + h] = lm[h];
    __syncthreads();
    for (int off = 128; off > 0; off >>= 1){
        if (tid < off)
            #pragma unroll
            for (int h = 0; h < H_H; h++)
                red[tid*H_H+h] = fmaxf(red[tid*H_H+h], red[(tid+off)*H_H+h]);
        __syncthreads();
    }
    if (tid < H_H) mval[tid] = red[tid];
    __syncthreads();

    float ls[H_H];
    #pragma unroll
    for (int h = 0; h < H_H; h++) ls[h] = 0.f;
    for (int r = tid; r < len; r += 256){
        const int n = start + r;
        #pragma unroll
        for (int h = 0; h < H_H; h++) ls[h] += expf(g_h[(size_t)n*H_H+h] - mval[h]);
    }
    #pragma unroll
    for (int h = 0; h < H_H; h++) red[tid*H_H + h] = ls[h];
    __syncthreads();
    for (int off = 128; off > 0; off >>= 1){
        if (tid < off)
            #pragma unroll
            for (int h = 0; h < H_H; h++)
                red[tid*H_H+h] += red[(tid+off)*H_H+h];
        __syncthreads();
    }
    if (tid < H_H) sval[tid] = red[tid];
    __syncthreads();

    float inv[H_H];
    #pragma unroll
    for (int h = 0; h < H_H; h++) inv[h] = 1.f / sval[h];
    for (int r = tid; r < len; r += 256){
        const int n = start + r;
        #pragma unroll
        for (int h = 0; h < H_H; h++)
            g_attn[(size_t)n*H_H+h] = expf(g_h[(size_t)n*H_H+h] - mval[h]) * inv[h];
    }
}

// ---------------- 4: pooling split over rows -----------------------------------
__global__ __launch_bounds__(256) void k_pool(const float* __restrict__ x){
    const int b = blockIdx.x;
    const int d = blockIdx.y * 256 + threadIdx.x;
    const int chunk = blockIdx.z;
    const int start = g_segstart[b];
    const int len = g_segstart[b+1] - start;
    const int cl = (len + PSPL - 1) / PSPL;
    const int r0b = chunk * cl;
    const int r1b = min(len, r0b + cl);

    __shared__ float sat[32][H_H];
    float acc[H_H];
    #pragma unroll
    for (int h = 0; h < H_H; h++) acc[h] = 0.f;
    float ssum = 0.f;

    for (int r0 = r0b; r0 < r1b; r0 += 32){
        const int cnt = min(32, r1b - r0);
        if (threadIdx.x < cnt * H_H){
            const int rr = threadIdx.x >> 3, hh = threadIdx.x & 7;
            sat[rr][hh] = g_attn[(size_t)(start + r0 + rr) * H_H + hh];
        }
        __syncthreads();
        for (int rr = 0; rr < cnt; rr++){
            const float xv = x[(size_t)(start + r0 + rr) * D_EMB + d];
            ssum += xv;
            #pragma unroll
            for (int h = 0; h < H_H; h++) acc[h] = fmaf(xv, sat[rr][h], acc[h]);
        }
        __syncthreads();
    }
    #pragma unroll
    for (int h = 0; h < H_H; h++)
        g_poolpart[chunk][(size_t)b * DH + d * H_H + h] = acc[h];
    g_msumpart[chunk][(size_t)b * D_EMB + d] = ssum;
}

__global__ __launch_bounds__(256) void k_poolred(float* __restrict__ out){
    const int i = blockIdx.x * 256 + threadIdx.x;   // 65536
    const int b = i >> 10, d = i & 1023;
    float acc[H_H];
    #pragma unroll
    for (int h = 0; h < H_H; h++) acc[h] = 0.f;
    float s = 0.f;
    #pragma unroll
    for (int p = 0; p < PSPL; p++){
        #pragma unroll
        for (int h = 0; h < H_H; h++)
            acc[h] += g_poolpart[p][(size_t)b * DH + d * H_H + h];
        s += g_msumpart[p][(size_t)b * D_EMB + d];
    }
    #pragma unroll
    for (int h = 0; h < H_H; h++)
        g_obdh[(size_t)b * DH + d * H_H + h] = acc[h];
    const int len = g_segstart[b+1] - g_segstart[b];
    out[B_SEG * D_EMB + i] = s / (float)len;
}

// ---------------- 5: attn gram --------------------------------------------------
__global__ void k_gram(float* __restrict__ out){
    const int b = blockIdx.x, tid = threadIdx.x;   // 64
    const int i = tid >> 3, j = tid & 7;
    const int start = g_segstart[b];
    const int len = g_segstart[b+1] - start;
    float acc = 0.f;
    for (int r = 0; r < len; r++){
        const float* a = &g_attn[(size_t)(start + r) * H_H];
        acc = fmaf(a[i], a[j], acc);
    }
    out[2 * B_SEG * D_EMB + b * 64 + tid] = acc;
}

// ---------------- 6: post GEMM (64x1024x8192) -----------------------------------
__global__ __launch_bounds__(256) void k_post(const float* __restrict__ wp){
    __shared__ float As[16][72];
    __shared__ float Ws[16][72];
    const int tid = threadIdx.x;
    const int tx = tid & 15, ty = tid >> 4;
    const int j0 = blockIdx.x * 64;
    const int ks = blockIdx.y;
    const int kbase = ks * 1024;

    float acc[4][4];
    #pragma unroll
    for (int i = 0; i < 4; i++)
        #pragma unroll
        for (int j = 0; j < 4; j++) acc[i][j] = 0.f;

    for (int kc = 0; kc < 64; kc++){
        const int k0 = kbase + kc * 16;
        {
            const int row = tid >> 2, q = tid & 3;
            float4 v = *(const float4*)&g_obdh[(size_t)row * DH + k0 + q * 4];
            As[q*4+0][row] = v.x; As[q*4+1][row] = v.y;
            As[q*4+2][row] = v.z; As[q*4+3][row] = v.w;
        }
        {
            const int row = tid >> 4, q = tid & 15;
            float4 v = *(const float4*)&wp[(size_t)(k0 + row) * D_EMB + j0 + q * 4];
            *(float4*)&Ws[row][q * 4] = v;
        }
        __syncthreads();
        #pragma unroll
        for (int k = 0; k < 16; k++){
            float4 av = *(const float4*)&As[k][ty * 4];
            float4 wv = *(const float4*)&Ws[k][tx * 4];
            float ar[4] = {av.x, av.y, av.z, av.w};
            float wr[4] = {wv.x, wv.y, wv.z, wv.w};
            #pragma unroll
            for (int i = 0; i < 4; i++)
                #pragma unroll
                for (int j = 0; j < 4; j++)
                    acc[i][j] = fmaf(ar[i], wr[j], acc[i][j]);
        }
        __syncthreads();
    }
    #pragma unroll
    for (int i = 0; i < 4; i++)
        #pragma unroll
        for (int j = 0; j < 4; j++)
            g_outpart[ks][(size_t)(ty*4 + i) * D_EMB + j0 + tx*4 + j] = acc[i][j];
}

__global__ void k_redout(float* __restrict__ out){
    const int i = blockIdx.x * 256 + threadIdx.x;
    float s = 0.f;
    #pragma unroll
    for (int p = 0; p < 8; p++) s += g_outpart[p][i];
    out[i] = s;
}

// ---------------- launch ----------------------------------------------------------
extern "C" void kernel_launch(void* const* d_in, const int* in_sizes, int n_in,
                              void* d_out, int out_size)
{
    const float* x   = (const float*)d_in[0];
    const int*   seg = (const int*)  d_in[1];
    const float* w1  = (const float*)d_in[2];
    const float* w2  = (const float*)d_in[3];
    const float* wp  = (const float*)d_in[4];
    float* out = (float*)d_out;

    cudaFuncSetAttribute(k_mma1, cudaFuncAttributeMaxDynamicSharedMemorySize, SM_TOT);

    k_prefix  <<<1, 32>>>(seg);
    k_splitx  <<<N_FR*D_EMB/1024, 256>>>(x);
    k_splitw  <<<dim3(A_DIM/32, D_EMB/32), dim3(32, 8)>>>(w1);
    k_mma1    <<<dim3(N_FR/128, NTA), 256, SM_TOT>>>(w2);
    k_softmax <<<B_SEG, 256>>>();
    k_pool    <<<dim3(B_SEG, 4, PSPL), 256>>>(x);
    k_poolred <<<B_SEG*D_EMB/256, 256>>>(out);
    k_gram    <<<B_SEG, 64>>>(out);
    k_post    <<<dim3(16, 8), 256>>>(wp);
    k_redout  <<<B_SEG*D_EMB/256, 256>>>(out);
}

// round 6
// speedup vs baseline: 2.8425x; 1.0749x over previous
#include <cuda_runtime.h>
#include <cuda_bf16.h>
#include <math.h>
#include <stdint.h>

#define N_FR   16384
#define D_EMB  1024
#define A_DIM  2048
#define H_H    8
#define B_SEG  64
#define DH     (D_EMB*H_H)
#define NTA    16         // a-tiles of 128
#define PSPL   8          // pool row-splits

// ---------------- scratch ---------------------------------------------------
__device__ __align__(128) __nv_bfloat16 g_xhi[N_FR*D_EMB];
__device__ __align__(128) __nv_bfloat16 g_xlo[N_FR*D_EMB];
__device__ __align__(128) __nv_bfloat16 g_w1hi[A_DIM*D_EMB];   // transposed [A, D]
__device__ __align__(128) __nv_bfloat16 g_w1lo[A_DIM*D_EMB];
__device__ float g_hpart[NTA][N_FR*H_H];
__device__ float g_h[N_FR*H_H];
__device__ float g_attn[N_FR*H_H];
__device__ float g_obdh[B_SEG*DH];
__device__ float g_poolpart[PSPL][B_SEG*DH];
__device__ float g_msumpart[PSPL][B_SEG*D_EMB];
__device__ float g_outpart[8][B_SEG*D_EMB];
__device__ int   g_segstart[B_SEG+1];

// ---------------- helpers ----------------------------------------------------
__device__ __forceinline__ uint32_t smem_u32(const void* p){
    uint32_t a;
    asm("{ .reg .u64 t; cvta.to.shared.u64 t, %1; cvt.u32.u64 %0, t; }" : "=r"(a) : "l"(p));
    return a;
}
__device__ __forceinline__ void cpa16(uint32_t dst, const void* src){
    asm volatile("cp.async.cg.shared.global [%0], [%1], 16;\n" :: "r"(dst), "l"(src));
}
__device__ __forceinline__ void cpa_commit(){ asm volatile("cp.async.commit_group;\n" ::: "memory"); }
__device__ __forceinline__ void cpa_wait1(){ asm volatile("cp.async.wait_group 1;\n" ::: "memory"); }
__device__ __forceinline__ void cpa_wait0(){ asm volatile("cp.async.wait_group 0;\n" ::: "memory"); }

__device__ __forceinline__ void ldm_x4(uint32_t* r, uint32_t addr){
    asm volatile("ldmatrix.sync.aligned.m8n8.x4.shared.b16 {%0,%1,%2,%3}, [%4];"
        : "=r"(r[0]),"=r"(r[1]),"=r"(r[2]),"=r"(r[3]) : "r"(addr));
}
__device__ __forceinline__ void ldm_x2(uint32_t* r, uint32_t addr){
    asm volatile("ldmatrix.sync.aligned.m8n8.x2.shared.b16 {%0,%1}, [%2];"
        : "=r"(r[0]),"=r"(r[1]) : "r"(addr));
}
__device__ __forceinline__ void mma_bf16(float* d, const uint32_t* a, const uint32_t* b){
    asm volatile("mma.sync.aligned.m16n8k16.row.col.f32.bf16.bf16.f32 "
        "{%0,%1,%2,%3}, {%4,%5,%6,%7}, {%8,%9}, {%0,%1,%2,%3};"
        : "+f"(d[0]),"+f"(d[1]),"+f"(d[2]),"+f"(d[3])
        : "r"(a[0]),"r"(a[1]),"r"(a[2]),"r"(a[3]), "r"(b[0]),"r"(b[1]));
}

// ---------------- 0: prefix sum ---------------------------------------------
__global__ void k_prefix(const int* __restrict__ seg){
    if (threadIdx.x == 0){
        int acc = 0; g_segstart[0] = 0;
        for (int i = 0; i < B_SEG; i++){ acc += seg[i]; g_segstart[i+1] = acc; }
    }
}

// ---------------- 1a: split x into bf16 hi/lo ---------------------------------
__global__ __launch_bounds__(256) void k_splitx(const float* __restrict__ x){
    size_t i = ((size_t)blockIdx.x * 256 + threadIdx.x) * 4;
    float4 v = *(const float4*)(x + i);
    float vv[4] = {v.x, v.y, v.z, v.w};
    __nv_bfloat16 h[4], l[4];
    #pragma unroll
    for (int j = 0; j < 4; j++){
        h[j] = __float2bfloat16(vv[j]);
        l[j] = __float2bfloat16(vv[j] - __bfloat162float(h[j]));
    }
    *(__nv_bfloat162*)&g_xhi[i]   = __nv_bfloat162(h[0], h[1]);
    *(__nv_bfloat162*)&g_xhi[i+2] = __nv_bfloat162(h[2], h[3]);
    *(__nv_bfloat162*)&g_xlo[i]   = __nv_bfloat162(l[0], l[1]);
    *(__nv_bfloat162*)&g_xlo[i+2] = __nv_bfloat162(l[2], l[3]);
}

// ---------------- 1b: transpose + split w1 ------------------------------------
__global__ void k_splitw(const float* __restrict__ w1){
    __shared__ float t[32][33];
    int a0 = blockIdx.x * 32, k0 = blockIdx.y * 32;
    int tx = threadIdx.x, ty = threadIdx.y;   // (32, 8)
    #pragma unroll
    for (int i = 0; i < 4; i++)
        t[ty + i*8][tx] = w1[(size_t)(k0 + ty + i*8) * A_DIM + a0 + tx];
    __syncthreads();
    #pragma unroll
    for (int i = 0; i < 4; i++){
        int al = ty + i*8;
        float v = t[tx][al];
        __nv_bfloat16 h = __float2bfloat16(v);
        g_w1hi[(size_t)(a0 + al) * D_EMB + k0 + tx] = h;
        g_w1lo[(size_t)(a0 + al) * D_EMB + k0 + tx] =
            __float2bfloat16(v - __bfloat162float(h));
    }
}

// ---------------- 2: bf16x3 MMA GEMM + fused relu@w2 epilogue -----------------
// CTA 128m x 128a, 8 warps (2x4), warp tile 64x32, K chunks of 32.
// 64B rows, XOR swizzle s(r)=(r>>1)&3: slot=(4r+(j^s))%8 is a permutation over
// 8 consecutive rows -> conflict-free LDSM phases. 3-stage pipe, 1 sync/chunk.
#define ROWB   64                 // row stride in bytes (32 bf16, swizzled)
#define ARR_SZ (128*ROWB)         // 8192 B per operand array
#define STG_SZ (4*ARR_SZ)         // XH|XL|WH|WL = 32768 B
#define OFF_XH 0
#define OFF_XL (1*ARR_SZ)
#define OFF_WH (2*ARR_SZ)
#define OFF_WL (3*ARR_SZ)
#define OFF_C  0                            // union with stage buffers
#define C_LD   136                          // fp32 words per C row (128+8 pad)
#define OFF_W2 (3*STG_SZ)                   // 98304
#define SM_TOT (OFF_W2 + 128*H_H*4)         // 102400

// swizzled byte offset of (row, 16B-chunk j) within one operand array
__device__ __forceinline__ uint32_t swz(int row, int j){
    return (uint32_t)(row * ROWB + ((j ^ ((row >> 1) & 3)) << 4));
}

__device__ __forceinline__ void load_chunk(uint32_t sbuf, int c, int m0, int a0){
    const int tid = threadIdx.x;
    const int row = tid >> 1;
    const int j0  = (tid & 1) * 2;          // 16B chunks j0, j0+1
    const size_t xo = (size_t)(m0 + row) * D_EMB + c * 32;
    const size_t wo = (size_t)(a0 + row) * D_EMB + c * 32;
    #pragma unroll
    for (int j = j0; j < j0 + 2; j++){
        const uint32_t so = swz(row, j);
        cpa16(sbuf + OFF_XH + so, g_xhi  + xo + j * 8);
        cpa16(sbuf + OFF_XL + so, g_xlo  + xo + j * 8);
        cpa16(sbuf + OFF_WH + so, g_w1hi + wo + j * 8);
        cpa16(sbuf + OFF_WL + so, g_w1lo + wo + j * 8);
    }
    cpa_commit();
}

__global__ void __launch_bounds__(256, 2) k_mma1(const float* __restrict__ w2){
    extern __shared__ char smem[];
    const uint32_t sb = smem_u32(smem);
    float* Cs  = (float*)(smem + OFF_C);
    float* W2s = (float*)(smem + OFF_W2);
    const int tid = threadIdx.x;
    const int wid = tid >> 5, lane = tid & 31;
    const int wm = wid >> 2, wn = wid & 3;       // warp grid 2x4
    const int grp = lane >> 2, t4 = lane & 3;
    const int m0 = blockIdx.x * 128;
    const int a0 = blockIdx.y * 128;

    for (int i = tid; i < 128 * H_H; i += 256)
        W2s[i] = w2[(size_t)(a0 + (i >> 3)) * H_H + (i & 7)];

    float acc[4][4][4];
    #pragma unroll
    for (int mt = 0; mt < 4; mt++)
        #pragma unroll
        for (int nt = 0; nt < 4; nt++)
            #pragma unroll
            for (int j = 0; j < 4; j++) acc[mt][nt][j] = 0.f;

    load_chunk(sb + 0*STG_SZ, 0, m0, a0);
    load_chunk(sb + 1*STG_SZ, 1, m0, a0);

    // ldmatrix lane addressing constants
    const int a_row = (lane & 15);          // row within 16-row A tile
    const int a_jh  = (lane >> 4);          // 16B-chunk half select (0/1)
    const int b_row = (lane & 7);
    const int b_jh  = ((lane >> 3) & 1);

    uint32_t base = sb;                     // stage 0
    for (int c = 0; c < 32; c++){
        if (c == 31) cpa_wait0(); else cpa_wait1();
        __syncthreads();
        if (c + 2 < 32)
            load_chunk(sb + ((c + 2) % 3) * STG_SZ, c + 2, m0, a0);

        #pragma unroll
        for (int kk = 0; kk < 2; kk++){
            const int jb = kk * 2;          // first 16B chunk of this k16
            // hi A + hi B, hh MMAs
            uint32_t ah[4][4];
            #pragma unroll
            for (int mt = 0; mt < 4; mt++){
                int r = wm * 64 + mt * 16 + a_row;
                ldm_x4(ah[mt], base + OFF_XH + swz(r, jb + a_jh));
            }
            uint32_t bh[4][2];
            #pragma unroll
            for (int nt = 0; nt < 4; nt++){
                int r = wn * 32 + nt * 8 + b_row;
                ldm_x2(bh[nt], base + OFF_WH + swz(r, jb + b_jh));
            }
            #pragma unroll
            for (int mt = 0; mt < 4; mt++)
                #pragma unroll
                for (int nt = 0; nt < 4; nt++)
                    mma_bf16(acc[mt][nt], ah[mt], bh[nt]);
            // lo B, h*l MMAs
            {
                uint32_t bl[4][2];
                #pragma unroll
                for (int nt = 0; nt < 4; nt++){
                    int r = wn * 32 + nt * 8 + b_row;
                    ldm_x2(bl[nt], base + OFF_WL + swz(r, jb + b_jh));
                }
                #pragma unroll
                for (int mt = 0; mt < 4; mt++)
                    #pragma unroll
                    for (int nt = 0; nt < 4; nt++)
                        mma_bf16(acc[mt][nt], ah[mt], bl[nt]);
            }
            // lo A, l*h MMAs
            {
                uint32_t al[4][4];
                #pragma unroll
                for (int mt = 0; mt < 4; mt++){
                    int r = wm * 64 + mt * 16 + a_row;
                    ldm_x4(al[mt], base + OFF_XL + swz(r, jb + a_jh));
                }
                #pragma unroll
                for (int mt = 0; mt < 4; mt++)
                    #pragma unroll
                    for (int nt = 0; nt < 4; nt++)
                        mma_bf16(acc[mt][nt], al[mt], bh[nt]);
            }
        }
        base = sb + ((c + 1) % 3) * STG_SZ;
    }
    __syncthreads();   // all warps done reading buffers before C overwrites them

    // relu(C) -> smem (union region)
    #pragma unroll
    for (int mt = 0; mt < 4; mt++)
        #pragma unroll
        for (int nt = 0; nt < 4; nt++){
            const int r0 = wm * 64 + mt * 16 + grp;
            const int c0 = wn * 32 + nt * 8 + t4 * 2;
            Cs[(r0    ) * C_LD + c0    ] = fmaxf(acc[mt][nt][0], 0.f);
            Cs[(r0    ) * C_LD + c0 + 1] = fmaxf(acc[mt][nt][1], 0.f);
            Cs[(r0 + 8) * C_LD + c0    ] = fmaxf(acc[mt][nt][2], 0.f);
            Cs[(r0 + 8) * C_LD + c0 + 1] = fmaxf(acc[mt][nt][3], 0.f);
        }
    __syncthreads();

    // h partial: relu(C)[128x128] @ w2slice[128x8]
    #pragma unroll
    for (int it = 0; it < 4; it++){
        const int idx = tid + it * 256;
        const int row = idx >> 3, h = idx & 7;
        float s = 0.f;
        #pragma unroll 8
        for (int cc = 0; cc < 128; cc++)
            s = fmaf(Cs[row * C_LD + cc], W2s[cc * H_H + h], s);
        g_hpart[blockIdx.y][(size_t)(m0 + row) * H_H + h] = s;
    }
}

// ---------------- 3: per-segment softmax (combines 16 partials) ---------------
__global__ __launch_bounds__(256) void k_softmax(){
    const int b = blockIdx.x, tid = threadIdx.x;
    const int start = g_segstart[b];
    const int len = g_segstart[b+1] - start;
    __shared__ float red[256 * H_H];
    __shared__ float mval[H_H], sval[H_H];

    float lm[H_H];
    #pragma unroll
    for (int h = 0; h < H_H; h++) lm[h] = -1e30f;
    for (int r = tid; r < len; r += 256){
        const int n = start + r;
        #pragma unroll
        for (int h = 0; h < H_H; h++){
            float v = 0.f;
            #pragma unroll
            for (int p = 0; p < NTA; p++) v += g_hpart[p][(size_t)n*H_H + h];
            g_h[(size_t)n*H_H + h] = v;
            lm[h] = fmaxf(lm[h], v);
        }
    }
    #pragma unroll
    for (int h = 0; h < H_H; h++) red[tid*H_H + h] = lm[h];
    __syncthreads();
    for (int off = 128; off > 0; off >>= 1){
        if (tid < off)
            #pragma unroll
            for (int h = 0; h < H_H; h++)
                red[tid*H_H+h] = fmaxf(red[tid*H_H+h], red[(tid+off)*H_H+h]);
        __syncthreads();
    }
    if (tid < H_H) mval[tid] = red[tid];
    __syncthreads();

    float ls[H_H];
    #pragma unroll
    for (int h = 0; h < H_H; h++) ls[h] = 0.f;
    for (int r = tid; r < len; r += 256){
        const int n = start + r;
        #pragma unroll
        for (int h = 0; h < H_H; h++) ls[h] += expf(g_h[(size_t)n*H_H+h] - mval[h]);
    }
    #pragma unroll
    for (int h = 0; h < H_H; h++) red[tid*H_H + h] = ls[h];
    __syncthreads();
    for (int off = 128; off > 0; off >>= 1){
        if (tid < off)
            #pragma unroll
            for (int h = 0; h < H_H; h++)
                red[tid*H_H+h] += red[(tid+off)*H_H+h];
        __syncthreads();
    }
    if (tid < H_H) sval[tid] = red[tid];
    __syncthreads();

    float inv[H_H];
    #pragma unroll
    for (int h = 0; h < H_H; h++) inv[h] = 1.f / sval[h];
    for (int r = tid; r < len; r += 256){
        const int n = start + r;
        #pragma unroll
        for (int h = 0; h < H_H; h++)
            g_attn[(size_t)n*H_H+h] = expf(g_h[(size_t)n*H_H+h] - mval[h]) * inv[h];
    }
}

// ---------------- 4: pooling split over rows -----------------------------------
__global__ __launch_bounds__(256) void k_pool(const float* __restrict__ x){
    const int b = blockIdx.x;
    const int d = blockIdx.y * 256 + threadIdx.x;
    const int chunk = blockIdx.z;
    const int start = g_segstart[b];
    const int len = g_segstart[b+1] - start;
    const int cl = (len + PSPL - 1) / PSPL;
    const int r0b = chunk * cl;
    const int r1b = min(len, r0b + cl);

    __shared__ float sat[32][H_H];
    float acc[H_H];
    #pragma unroll
    for (int h = 0; h < H_H; h++) acc[h] = 0.f;
    float ssum = 0.f;

    for (int r0 = r0b; r0 < r1b; r0 += 32){
        const int cnt = min(32, r1b - r0);
        if (threadIdx.x < cnt * H_H){
            const int rr = threadIdx.x >> 3, hh = threadIdx.x & 7;
            sat[rr][hh] = g_attn[(size_t)(start + r0 + rr) * H_H + hh];
        }
        __syncthreads();
        for (int rr = 0; rr < cnt; rr++){
            const float xv = x[(size_t)(start + r0 + rr) * D_EMB + d];
            ssum += xv;
            #pragma unroll
            for (int h = 0; h < H_H; h++) acc[h] = fmaf(xv, sat[rr][h], acc[h]);
        }
        __syncthreads();
    }
    #pragma unroll
    for (int h = 0; h < H_H; h++)
        g_poolpart[chunk][(size_t)b * DH + d * H_H + h] = acc[h];
    g_msumpart[chunk][(size_t)b * D_EMB + d] = ssum;
}

__global__ __launch_bounds__(256) void k_poolred(float* __restrict__ out){
    const int i = blockIdx.x * 256 + threadIdx.x;   // 65536
    const int b = i >> 10, d = i & 1023;
    float acc[H_H];
    #pragma unroll
    for (int h = 0; h < H_H; h++) acc[h] = 0.f;
    float s = 0.f;
    #pragma unroll
    for (int p = 0; p < PSPL; p++){
        #pragma unroll
        for (int h = 0; h < H_H; h++)
            acc[h] += g_poolpart[p][(size_t)b * DH + d * H_H + h];
        s += g_msumpart[p][(size_t)b * D_EMB + d];
    }
    #pragma unroll
    for (int h = 0; h < H_H; h++)
        g_obdh[(size_t)b * DH + d * H_H + h] = acc[h];
    const int len = g_segstart[b+1] - g_segstart[b];
    out[B_SEG * D_EMB + i] = s / (float)len;
}

// ---------------- 5: attn gram --------------------------------------------------
__global__ void k_gram(float* __restrict__ out){
    const int b = blockIdx.x, tid = threadIdx.x;   // 64
    const int i = tid >> 3, j = tid & 7;
    const int start = g_segstart[b];
    const int len = g_segstart[b+1] - start;
    float acc = 0.f;
    for (int r = 0; r < len; r++){
        const float* a = &g_attn[(size_t)(start + r) * H_H];
        acc = fmaf(a[i], a[j], acc);
    }
    out[2 * B_SEG * D_EMB + b * 64 + tid] = acc;
}

// ---------------- 6: post GEMM (64x1024x8192) -----------------------------------
__global__ __launch_bounds__(256) void k_post(const float* __restrict__ wp){
    __shared__ float As[16][72];
    __shared__ float Ws[16][72];
    const int tid = threadIdx.x;
    const int tx = tid & 15, ty = tid >> 4;
    const int j0 = blockIdx.x * 64;
    const int ks = blockIdx.y;
    const int kbase = ks * 1024;

    float acc[4][4];
    #pragma unroll
    for (int i = 0; i < 4; i++)
        #pragma unroll
        for (int j = 0; j < 4; j++) acc[i][j] = 0.f;

    for (int kc = 0; kc < 64; kc++){
        const int k0 = kbase + kc * 16;
        {
            const int row = tid >> 2, q = tid & 3;
            float4 v = *(const float4*)&g_obdh[(size_t)row * DH + k0 + q * 4];
            As[q*4+0][row] = v.x; As[q*4+1][row] = v.y;
            As[q*4+2][row] = v.z; As[q*4+3][row] = v.w;
        }
        {
            const int row = tid >> 4, q = tid & 15;
            float4 v = *(const float4*)&wp[(size_t)(k0 + row) * D_EMB + j0 + q * 4];
            *(float4*)&Ws[row][q * 4] = v;
        }
        __syncthreads();
        #pragma unroll
        for (int k = 0; k < 16; k++){
            float4 av = *(const float4*)&As[k][ty * 4];
            float4 wv = *(const float4*)&Ws[k][tx * 4];
            float ar[4] = {av.x, av.y, av.z, av.w};
            float wr[4] = {wv.x, wv.y, wv.z, wv.w};
            #pragma unroll
            for (int i = 0; i < 4; i++)
                #pragma unroll
                for (int j = 0; j < 4; j++)
                    acc[i][j] = fmaf(ar[i], wr[j], acc[i][j]);
        }
        __syncthreads();
    }
    #pragma unroll
    for (int i = 0; i < 4; i++)
        #pragma unroll
        for (int j = 0; j < 4; j++)
            g_outpart[ks][(size_t)(ty*4 + i) * D_EMB + j0 + tx*4 + j] = acc[i][j];
}

__global__ void k_redout(float* __restrict__ out){
    const int i = blockIdx.x * 256 + threadIdx.x;
    float s = 0.f;
    #pragma unroll
    for (int p = 0; p < 8; p++) s += g_outpart[p][i];
    out[i] = s;
}

// ---------------- launch ----------------------------------------------------------
extern "C" void kernel_launch(void* const* d_in, const int* in_sizes, int n_in,
                              void* d_out, int out_size)
{
    const float* x   = (const float*)d_in[0];
    const int*   seg = (const int*)  d_in[1];
    const float* w1  = (const float*)d_in[2];
    const float* w2  = (const float*)d_in[3];
    const float* wp  = (const float*)d_in[4];
    float* out = (float*)d_out;

    cudaFuncSetAttribute(k_mma1, cudaFuncAttributeMaxDynamicSharedMemorySize, SM_TOT);

    k_prefix  <<<1, 32>>>(seg);
    k_splitx  <<<N_FR*D_EMB/1024, 256>>>(x);
    k_splitw  <<<dim3(A_DIM/32, D_EMB/32), dim3(32, 8)>>>(w1);
    k_mma1    <<<dim3(N_FR/128, NTA), 256, SM_TOT>>>(w2);
    k_softmax <<<B_SEG, 256>>>();
    k_pool    <<<dim3(B_SEG, 4, PSPL), 256>>>(x);
    k_poolred <<<B_SEG*D_EMB/256, 256>>>(out);
    k_gram    <<<B_SEG, 64>>>(out);
    k_post    <<<dim3(16, 8), 256>>>(wp);
    k_redout  <<<B_SEG*D_EMB/256, 256>>>(out);
}

// round 7
// speedup vs baseline: 2.8840x; 1.0146x over previous
#include <cuda_runtime.h>
#include <cuda_bf16.h>
#include <math.h>
#include <stdint.h>

#define N_FR   16384
#define D_EMB  1024
#define A_DIM  2048
#define H_H    8
#define B_SEG  64
#define DH     (D_EMB*H_H)
#define NTA    16         // a-tiles of 128
#define PSPL   8          // pool row-splits

// ---------------- scratch ---------------------------------------------------
__device__ __align__(128) __nv_bfloat16 g_xhi[N_FR*D_EMB];
__device__ __align__(128) __nv_bfloat16 g_xlo[N_FR*D_EMB];
__device__ __align__(128) __nv_bfloat16 g_w1hi[A_DIM*D_EMB];   // transposed [A, D]
__device__ __align__(128) __nv_bfloat16 g_w1lo[A_DIM*D_EMB];
__device__ float g_hpart[NTA][N_FR*H_H];
__device__ float g_h[N_FR*H_H];
__device__ float g_attn[N_FR*H_H];
__device__ float g_obdh[B_SEG*DH];
__device__ float g_poolpart[PSPL][B_SEG*DH];
__device__ float g_msumpart[PSPL][B_SEG*D_EMB];
__device__ float g_outpart[8][B_SEG*D_EMB];
__device__ int   g_segstart[B_SEG+1];

// ---------------- helpers ----------------------------------------------------
__device__ __forceinline__ uint32_t smem_u32(const void* p){
    uint32_t a;
    asm("{ .reg .u64 t; cvta.to.shared.u64 t, %1; cvt.u32.u64 %0, t; }" : "=r"(a) : "l"(p));
    return a;
}
__device__ __forceinline__ void cpa16(uint32_t dst, const void* src){
    asm volatile("cp.async.cg.shared.global [%0], [%1], 16;\n" :: "r"(dst), "l"(src));
}
__device__ __forceinline__ void cpa_commit(){ asm volatile("cp.async.commit_group;\n" ::: "memory"); }
__device__ __forceinline__ void cpa_wait1(){ asm volatile("cp.async.wait_group 1;\n" ::: "memory"); }
__device__ __forceinline__ void cpa_wait0(){ asm volatile("cp.async.wait_group 0;\n" ::: "memory"); }

__device__ __forceinline__ void ldm_x4(uint32_t* r, uint32_t addr){
    asm volatile("ldmatrix.sync.aligned.m8n8.x4.shared.b16 {%0,%1,%2,%3}, [%4];"
        : "=r"(r[0]),"=r"(r[1]),"=r"(r[2]),"=r"(r[3]) : "r"(addr));
}
__device__ __forceinline__ void mma_bf16(float* d, const uint32_t* a, const uint32_t* b){
    asm volatile("mma.sync.aligned.m16n8k16.row.col.f32.bf16.bf16.f32 "
        "{%0,%1,%2,%3}, {%4,%5,%6,%7}, {%8,%9}, {%0,%1,%2,%3};"
        : "+f"(d[0]),"+f"(d[1]),"+f"(d[2]),"+f"(d[3])
        : "r"(a[0]),"r"(a[1]),"r"(a[2]),"r"(a[3]), "r"(b[0]),"r"(b[1]));
}

// ---------------- 0: prefix sum ---------------------------------------------
__global__ void k_prefix(const int* __restrict__ seg){
    if (threadIdx.x == 0){
        int acc = 0; g_segstart[0] = 0;
        for (int i = 0; i < B_SEG; i++){ acc += seg[i]; g_segstart[i+1] = acc; }
    }
}

// ---------------- 1a: split x into bf16 hi/lo ---------------------------------
__global__ __launch_bounds__(256) void k_splitx(const float* __restrict__ x){
    size_t i = ((size_t)blockIdx.x * 256 + threadIdx.x) * 4;
    float4 v = *(const float4*)(x + i);
    float vv[4] = {v.x, v.y, v.z, v.w};
    __nv_bfloat16 h[4], l[4];
    #pragma unroll
    for (int j = 0; j < 4; j++){
        h[j] = __float2bfloat16(vv[j]);
        l[j] = __float2bfloat16(vv[j] - __bfloat162float(h[j]));
    }
    *(__nv_bfloat162*)&g_xhi[i]   = __nv_bfloat162(h[0], h[1]);
    *(__nv_bfloat162*)&g_xhi[i+2] = __nv_bfloat162(h[2], h[3]);
    *(__nv_bfloat162*)&g_xlo[i]   = __nv_bfloat162(l[0], l[1]);
    *(__nv_bfloat162*)&g_xlo[i+2] = __nv_bfloat162(l[2], l[3]);
}

// ---------------- 1b: transpose + split w1 ------------------------------------
__global__ void k_splitw(const float* __restrict__ w1){
    __shared__ float t[32][33];
    int a0 = blockIdx.x * 32, k0 = blockIdx.y * 32;
    int tx = threadIdx.x, ty = threadIdx.y;   // (32, 8)
    #pragma unroll
    for (int i = 0; i < 4; i++)
        t[ty + i*8][tx] = w1[(size_t)(k0 + ty + i*8) * A_DIM + a0 + tx];
    __syncthreads();
    #pragma unroll
    for (int i = 0; i < 4; i++){
        int al = ty + i*8;
        float v = t[tx][al];
        __nv_bfloat16 h = __float2bfloat16(v);
        g_w1hi[(size_t)(a0 + al) * D_EMB + k0 + tx] = h;
        g_w1lo[(size_t)(a0 + al) * D_EMB + k0 + tx] =
            __float2bfloat16(v - __bfloat162float(h));
    }
}

// ---------------- 2: bf16x3 MMA GEMM + fused relu@w2 epilogue -----------------
// CTA 128m x 128a, 8 warps (2x4), warp tile 64x32, K chunks of 32.
// 64B rows, XOR swizzle s(r)=(r>>1)&3 (conflict-free LDSM). 3-stage pipe,
// one __syncthreads per chunk. B frags via ldmatrix.x4 (nt-pair per instr).
#define ROWB   64                 // row stride in bytes (32 bf16, swizzled)
#define ARR_SZ (128*ROWB)         // 8192 B per operand array
#define STG_SZ (4*ARR_SZ)         // XH|XL|WH|WL = 32768 B
#define OFF_XH 0
#define OFF_XL (1*ARR_SZ)
#define OFF_WH (2*ARR_SZ)
#define OFF_WL (3*ARR_SZ)
#define OFF_C  0                            // union with stage buffers
#define C_LD   136                          // fp32 words per C row (128+8 pad)
#define OFF_W2 (3*STG_SZ)                   // 98304
#define SM_TOT (OFF_W2 + 128*H_H*4)         // 102400

// swizzled byte offset of (row, 16B-chunk j) within one operand array
__device__ __forceinline__ uint32_t swz(int row, int j){
    return (uint32_t)(row * ROWB + ((j ^ ((row >> 1) & 3)) << 4));
}

__device__ __forceinline__ void load_chunk(uint32_t sbuf, int c, int m0, int a0){
    const int tid = threadIdx.x;
    const int row = tid >> 1;
    const int j0  = (tid & 1) * 2;          // 16B chunks j0, j0+1
    const size_t xo = (size_t)(m0 + row) * D_EMB + c * 32;
    const size_t wo = (size_t)(a0 + row) * D_EMB + c * 32;
    #pragma unroll
    for (int j = j0; j < j0 + 2; j++){
        const uint32_t so = swz(row, j);
        cpa16(sbuf + OFF_XH + so, g_xhi  + xo + j * 8);
        cpa16(sbuf + OFF_XL + so, g_xlo  + xo + j * 8);
        cpa16(sbuf + OFF_WH + so, g_w1hi + wo + j * 8);
        cpa16(sbuf + OFF_WL + so, g_w1lo + wo + j * 8);
    }
    cpa_commit();
}

__global__ void __launch_bounds__(256, 2) k_mma1(const float* __restrict__ w2){
    extern __shared__ char smem[];
    const uint32_t sb = smem_u32(smem);
    float* Cs  = (float*)(smem + OFF_C);
    float* W2s = (float*)(smem + OFF_W2);
    const int tid = threadIdx.x;
    const int wid = tid >> 5, lane = tid & 31;
    const int wm = wid >> 2, wn = wid & 3;       // warp grid 2x4
    const int grp = lane >> 2, t4 = lane & 3;
    const int m0 = blockIdx.x * 128;
    const int a0 = blockIdx.y * 128;

    for (int i = tid; i < 128 * H_H; i += 256)
        W2s[i] = w2[(size_t)(a0 + (i >> 3)) * H_H + (i & 7)];

    float acc[4][4][4];
    #pragma unroll
    for (int mt = 0; mt < 4; mt++)
        #pragma unroll
        for (int nt = 0; nt < 4; nt++)
            #pragma unroll
            for (int j = 0; j < 4; j++) acc[mt][nt][j] = 0.f;

    load_chunk(sb + 0*STG_SZ, 0, m0, a0);
    load_chunk(sb + 1*STG_SZ, 1, m0, a0);

    // ldmatrix lane addressing constants
    const int a_row = (lane & 15);          // A: row within 16-row tile
    const int a_jh  = (lane >> 4);          // A: k-half select (0/1)
    // B x4: lanes 0-7 -> n-rows 0-7 k-half0, 8-15 -> k-half1,
    //       16-23 -> n-rows 8-15 k-half0, 24-31 -> k-half1
    const int b_row = (lane & 7) + ((lane >> 4) << 3);
    const int b_jh  = ((lane >> 3) & 1);

    uint32_t base = sb;                     // stage 0
    for (int c = 0; c < 32; c++){
        if (c == 31) cpa_wait0(); else cpa_wait1();
        __syncthreads();
        if (c + 2 < 32)
            load_chunk(sb + ((c + 2) % 3) * STG_SZ, c + 2, m0, a0);

        #pragma unroll
        for (int kk = 0; kk < 2; kk++){
            const int jb = kk * 2;          // first 16B chunk of this k16
            // ---- issue ALL frag loads upfront (12 LDSM) ----
            uint32_t ah[4][4], al[4][4];
            #pragma unroll
            for (int mt = 0; mt < 4; mt++){
                int r = wm * 64 + mt * 16 + a_row;
                ldm_x4(ah[mt], base + OFF_XH + swz(r, jb + a_jh));
            }
            uint32_t bh[2][4], bl[2][4];    // [np][4]: {n0k0,n0k8,n1k0,n1k8}
            #pragma unroll
            for (int np = 0; np < 2; np++){
                int r = wn * 32 + np * 16 + b_row;
                ldm_x4(bh[np], base + OFF_WH + swz(r, jb + b_jh));
            }
            #pragma unroll
            for (int np = 0; np < 2; np++){
                int r = wn * 32 + np * 16 + b_row;
                ldm_x4(bl[np], base + OFF_WL + swz(r, jb + b_jh));
            }
            #pragma unroll
            for (int mt = 0; mt < 4; mt++){
                int r = wm * 64 + mt * 16 + a_row;
                ldm_x4(al[mt], base + OFF_XL + swz(r, jb + a_jh));
            }
            // ---- 48 MMAs ----
            #pragma unroll
            for (int mt = 0; mt < 4; mt++)
                #pragma unroll
                for (int nt = 0; nt < 4; nt++)
                    mma_bf16(acc[mt][nt], ah[mt], &bh[nt >> 1][(nt & 1) * 2]);
            #pragma unroll
            for (int mt = 0; mt < 4; mt++)
                #pragma unroll
                for (int nt = 0; nt < 4; nt++)
                    mma_bf16(acc[mt][nt], ah[mt], &bl[nt >> 1][(nt & 1) * 2]);
            #pragma unroll
            for (int mt = 0; mt < 4; mt++)
                #pragma unroll
                for (int nt = 0; nt < 4; nt++)
                    mma_bf16(acc[mt][nt], al[mt], &bh[nt >> 1][(nt & 1) * 2]);
        }
        base = sb + ((c + 1) % 3) * STG_SZ;
    }
    __syncthreads();   // all warps done reading buffers before C overwrites them

    // relu(C) -> smem (union region)
    #pragma unroll
    for (int mt = 0; mt < 4; mt++)
        #pragma unroll
        for (int nt = 0; nt < 4; nt++){
            const int r0 = wm * 64 + mt * 16 + grp;
            const int c0 = wn * 32 + nt * 8 + t4 * 2;
            Cs[(r0    ) * C_LD + c0    ] = fmaxf(acc[mt][nt][0], 0.f);
            Cs[(r0    ) * C_LD + c0 + 1] = fmaxf(acc[mt][nt][1], 0.f);
            Cs[(r0 + 8) * C_LD + c0    ] = fmaxf(acc[mt][nt][2], 0.f);
            Cs[(r0 + 8) * C_LD + c0 + 1] = fmaxf(acc[mt][nt][3], 0.f);
        }
    __syncthreads();

    // h partial: relu(C)[128x128] @ w2slice[128x8]
    #pragma unroll
    for (int it = 0; it < 4; it++){
        const int idx = tid + it * 256;
        const int row = idx >> 3, h = idx & 7;
        float s = 0.f;
        #pragma unroll 8
        for (int cc = 0; cc < 128; cc++)
            s = fmaf(Cs[row * C_LD + cc], W2s[cc * H_H + h], s);
        g_hpart[blockIdx.y][(size_t)(m0 + row) * H_H + h] = s;
    }
}

// ---------------- 3: per-segment softmax (combines 16 partials) ---------------
__global__ __launch_bounds__(256) void k_softmax(){
    const int b = blockIdx.x, tid = threadIdx.x;
    const int start = g_segstart[b];
    const int len = g_segstart[b+1] - start;
    __shared__ float red[256 * H_H];
    __shared__ float mval[H_H], sval[H_H];

    float lm[H_H];
    #pragma unroll
    for (int h = 0; h < H_H; h++) lm[h] = -1e30f;
    for (int r = tid; r < len; r += 256){
        const int n = start + r;
        #pragma unroll
        for (int h = 0; h < H_H; h++){
            float v = 0.f;
            #pragma unroll
            for (int p = 0; p < NTA; p++) v += g_hpart[p][(size_t)n*H_H + h];
            g_h[(size_t)n*H_H + h] = v;
            lm[h] = fmaxf(lm[h], v);
        }
    }
    #pragma unroll
    for (int h = 0; h < H_H; h++) red[tid*H_H + h] = lm[h];
    __syncthreads();
    for (int off = 128; off > 0; off >>= 1){
        if (tid < off)
            #pragma unroll
            for (int h = 0; h < H_H; h++)
                red[tid*H_H+h] = fmaxf(red[tid*H_H+h], red[(tid+off)*H_H+h]);
        __syncthreads();
    }
    if (tid < H_H) mval[tid] = red[tid];
    __syncthreads();

    float ls[H_H];
    #pragma unroll
    for (int h = 0; h < H_H; h++) ls[h] = 0.f;
    for (int r = tid; r < len; r += 256){
        const int n = start + r;
        #pragma unroll
        for (int h = 0; h < H_H; h++) ls[h] += expf(g_h[(size_t)n*H_H+h] - mval[h]);
    }
    #pragma unroll
    for (int h = 0; h < H_H; h++) red[tid*H_H + h] = ls[h];
    __syncthreads();
    for (int off = 128; off > 0; off >>= 1){
        if (tid < off)
            #pragma unroll
            for (int h = 0; h < H_H; h++)
                red[tid*H_H+h] += red[(tid+off)*H_H+h];
        __syncthreads();
    }
    if (tid < H_H) sval[tid] = red[tid];
    __syncthreads();

    float inv[H_H];
    #pragma unroll
    for (int h = 0; h < H_H; h++) inv[h] = 1.f / sval[h];
    for (int r = tid; r < len; r += 256){
        const int n = start + r;
        #pragma unroll
        for (int h = 0; h < H_H; h++)
            g_attn[(size_t)n*H_H+h] = expf(g_h[(size_t)n*H_H+h] - mval[h]) * inv[h];
    }
}

// ---------------- 4: pooling split over rows -----------------------------------
__global__ __launch_bounds__(256) void k_pool(const float* __restrict__ x){
    const int b = blockIdx.x;
    const int d = blockIdx.y * 256 + threadIdx.x;
    const int chunk = blockIdx.z;
    const int start = g_segstart[b];
    const int len = g_segstart[b+1] - start;
    const int cl = (len + PSPL - 1) / PSPL;
    const int r0b = chunk * cl;
    const int r1b = min(len, r0b + cl);

    __shared__ float sat[32][H_H];
    float acc[H_H];
    #pragma unroll
    for (int h = 0; h < H_H; h++) acc[h] = 0.f;
    float ssum = 0.f;

    for (int r0 = r0b; r0 < r1b; r0 += 32){
        const int cnt = min(32, r1b - r0);
        if (threadIdx.x < cnt * H_H){
            const int rr = threadIdx.x >> 3, hh = threadIdx.x & 7;
            sat[rr][hh] = g_attn[(size_t)(start + r0 + rr) * H_H + hh];
        }
        __syncthreads();
        for (int rr = 0; rr < cnt; rr++){
            const float xv = x[(size_t)(start + r0 + rr) * D_EMB + d];
            ssum += xv;
            #pragma unroll
            for (int h = 0; h < H_H; h++) acc[h] = fmaf(xv, sat[rr][h], acc[h]);
        }
        __syncthreads();
    }
    #pragma unroll
    for (int h = 0; h < H_H; h++)
        g_poolpart[chunk][(size_t)b * DH + d * H_H + h] = acc[h];
    g_msumpart[chunk][(size_t)b * D_EMB + d] = ssum;
}

__global__ __launch_bounds__(256) void k_poolred(float* __restrict__ out){
    const int i = blockIdx.x * 256 + threadIdx.x;   // 65536
    const int b = i >> 10, d = i & 1023;
    float acc[H_H];
    #pragma unroll
    for (int h = 0; h < H_H; h++) acc[h] = 0.f;
    float s = 0.f;
    #pragma unroll
    for (int p = 0; p < PSPL; p++){
        #pragma unroll
        for (int h = 0; h < H_H; h++)
            acc[h] += g_poolpart[p][(size_t)b * DH + d * H_H + h];
        s += g_msumpart[p][(size_t)b * D_EMB + d];
    }
    #pragma unroll
    for (int h = 0; h < H_H; h++)
        g_obdh[(size_t)b * DH + d * H_H + h] = acc[h];
    const int len = g_segstart[b+1] - g_segstart[b];
    out[B_SEG * D_EMB + i] = s / (float)len;
}

// ---------------- 5: attn gram --------------------------------------------------
__global__ void k_gram(float* __restrict__ out){
    const int b = blockIdx.x, tid = threadIdx.x;   // 64
    const int i = tid >> 3, j = tid & 7;
    const int start = g_segstart[b];
    const int len = g_segstart[b+1] - start;
    float acc = 0.f;
    for (int r = 0; r < len; r++){
        const float* a = &g_attn[(size_t)(start + r) * H_H];
        acc = fmaf(a[i], a[j], acc);
    }
    out[2 * B_SEG * D_EMB + b * 64 + tid] = acc;
}

// ---------------- 6: post GEMM (64x1024x8192) -----------------------------------
__global__ __launch_bounds__(256) void k_post(const float* __restrict__ wp){
    __shared__ float As[16][72];
    __shared__ float Ws[16][72];
    const int tid = threadIdx.x;
    const int tx = tid & 15, ty = tid >> 4;
    const int j0 = blockIdx.x * 64;
    const int ks = blockIdx.y;
    const int kbase = ks * 1024;

    float acc[4][4];
    #pragma unroll
    for (int i = 0; i < 4; i++)
        #pragma unroll
        for (int j = 0; j < 4; j++) acc[i][j] = 0.f;

    for (int kc = 0; kc < 64; kc++){
        const int k0 = kbase + kc * 16;
        {
            const int row = tid >> 2, q = tid & 3;
            float4 v = *(const float4*)&g_obdh[(size_t)row * DH + k0 + q * 4];
            As[q*4+0][row] = v.x; As[q*4+1][row] = v.y;
            As[q*4+2][row] = v.z; As[q*4+3][row] = v.w;
        }
        {
            const int row = tid >> 4, q = tid & 15;
            float4 v = *(const float4*)&wp[(size_t)(k0 + row) * D_EMB + j0 + q * 4];
            *(float4*)&Ws[row][q * 4] = v;
        }
        __syncthreads();
        #pragma unroll
        for (int k = 0; k < 16; k++){
            float4 av = *(const float4*)&As[k][ty * 4];
            float4 wv = *(const float4*)&Ws[k][tx * 4];
            float ar[4] = {av.x, av.y, av.z, av.w};
            float wr[4] = {wv.x, wv.y, wv.z, wv.w};
            #pragma unroll
            for (int i = 0; i < 4; i++)
                #pragma unroll
                for (int j = 0; j < 4; j++)
                    acc[i][j] = fmaf(ar[i], wr[j], acc[i][j]);
        }
        __syncthreads();
    }
    #pragma unroll
    for (int i = 0; i < 4; i++)
        #pragma unroll
        for (int j = 0; j < 4; j++)
            g_outpart[ks][(size_t)(ty*4 + i) * D_EMB + j0 + tx*4 + j] = acc[i][j];
}

__global__ void k_redout(float* __restrict__ out){
    const int i = blockIdx.x * 256 + threadIdx.x;
    float s = 0.f;
    #pragma unroll
    for (int p = 0; p < 8; p++) s += g_outpart[p][i];
    out[i] = s;
}

// ---------------- launch ----------------------------------------------------------
extern "C" void kernel_launch(void* const* d_in, const int* in_sizes, int n_in,
                              void* d_out, int out_size)
{
    const float* x   = (const float*)d_in[0];
    const int*   seg = (const int*)  d_in[1];
    const float* w1  = (const float*)d_in[2];
    const float* w2  = (const float*)d_in[3];
    const float* wp  = (const float*)d_in[4];
    float* out = (float*)d_out;

    cudaFuncSetAttribute(k_mma1, cudaFuncAttributeMaxDynamicSharedMemorySize, SM_TOT);

    k_prefix  <<<1, 32>>>(seg);
    k_splitx  <<<N_FR*D_EMB/1024, 256>>>(x);
    k_splitw  <<<dim3(A_DIM/32, D_EMB/32), dim3(32, 8)>>>(w1);
    k_mma1    <<<dim3(N_FR/128, NTA), 256, SM_TOT>>>(w2);
    k_softmax <<<B_SEG, 256>>>();
    k_pool    <<<dim3(B_SEG, 4, PSPL), 256>>>(x);
    k_poolred <<<B_SEG*D_EMB/256, 256>>>(out);
    k_gram    <<<B_SEG, 64>>>(out);
    k_post    <<<dim3(16, 8), 256>>>(wp);
    k_redout  <<<B_SEG*D_EMB/256, 256>>>(out);
}

// round 8
// speedup vs baseline: 3.7337x; 1.2946x over previous
#include <cuda_runtime.h>
#include <cuda_fp16.h>
#include <math.h>
#include <stdint.h>

#define N_FR   16384
#define D_EMB  1024
#define A_DIM  2048
#define H_H    8
#define B_SEG  64
#define DH     (D_EMB*H_H)
#define NTA    16         // a-tiles of 128
#define PSPL   8          // pool row-splits

// ---------------- scratch ---------------------------------------------------
__device__ __align__(128) __half g_xh [N_FR*D_EMB];            // x in fp16 (single)
__device__ __align__(128) __half g_w1h[A_DIM*D_EMB];           // w1^T hi fp16
__device__ __align__(128) __half g_w1l[A_DIM*D_EMB];           // w1^T lo fp16
__device__ float g_hpart[NTA][N_FR*H_H];
__device__ float g_h[N_FR*H_H];
__device__ float g_attn[N_FR*H_H];
__device__ float g_obdh[B_SEG*DH];
__device__ float g_poolpart[PSPL][B_SEG*DH];
__device__ float g_msumpart[PSPL][B_SEG*D_EMB];
__device__ float g_outpart[8][B_SEG*D_EMB];
__device__ int   g_segstart[B_SEG+1];

// ---------------- helpers ----------------------------------------------------
__device__ __forceinline__ uint32_t smem_u32(const void* p){
    uint32_t a;
    asm("{ .reg .u64 t; cvta.to.shared.u64 t, %1; cvt.u32.u64 %0, t; }" : "=r"(a) : "l"(p));
    return a;
}
__device__ __forceinline__ void cpa16(uint32_t dst, const void* src){
    asm volatile("cp.async.cg.shared.global [%0], [%1], 16;\n" :: "r"(dst), "l"(src));
}
__device__ __forceinline__ void cpa_commit(){ asm volatile("cp.async.commit_group;\n" ::: "memory"); }
__device__ __forceinline__ void cpa_wait2(){ asm volatile("cp.async.wait_group 2;\n" ::: "memory"); }
__device__ __forceinline__ void cpa_wait1(){ asm volatile("cp.async.wait_group 1;\n" ::: "memory"); }
__device__ __forceinline__ void cpa_wait0(){ asm volatile("cp.async.wait_group 0;\n" ::: "memory"); }

__device__ __forceinline__ void ldm_x4(uint32_t* r, uint32_t addr){
    asm volatile("ldmatrix.sync.aligned.m8n8.x4.shared.b16 {%0,%1,%2,%3}, [%4];"
        : "=r"(r[0]),"=r"(r[1]),"=r"(r[2]),"=r"(r[3]) : "r"(addr));
}
__device__ __forceinline__ void mma_f16(float* d, const uint32_t* a, const uint32_t* b){
    asm volatile("mma.sync.aligned.m16n8k16.row.col.f32.f16.f16.f32 "
        "{%0,%1,%2,%3}, {%4,%5,%6,%7}, {%8,%9}, {%0,%1,%2,%3};"
        : "+f"(d[0]),"+f"(d[1]),"+f"(d[2]),"+f"(d[3])
        : "r"(a[0]),"r"(a[1]),"r"(a[2]),"r"(a[3]), "r"(b[0]),"r"(b[1]));
}

// ---------------- 0: prefix sum ---------------------------------------------
__global__ void k_prefix(const int* __restrict__ seg){
    if (threadIdx.x == 0){
        int acc = 0; g_segstart[0] = 0;
        for (int i = 0; i < B_SEG; i++){ acc += seg[i]; g_segstart[i+1] = acc; }
    }
}

// ---------------- 1a: x -> fp16 ------------------------------------------------
__global__ __launch_bounds__(256) void k_splitx(const float* __restrict__ x){
    size_t i = ((size_t)blockIdx.x * 256 + threadIdx.x) * 4;
    float4 v = *(const float4*)(x + i);
    __half2 a = __floats2half2_rn(v.x, v.y);
    __half2 b = __floats2half2_rn(v.z, v.w);
    *(__half2*)&g_xh[i]   = a;
    *(__half2*)&g_xh[i+2] = b;
}

// ---------------- 1b: transpose + fp16 hi/lo split of w1 -----------------------
__global__ void k_splitw(const float* __restrict__ w1){
    __shared__ float t[32][33];
    int a0 = blockIdx.x * 32, k0 = blockIdx.y * 32;
    int tx = threadIdx.x, ty = threadIdx.y;   // (32, 8)
    #pragma unroll
    for (int i = 0; i < 4; i++)
        t[ty + i*8][tx] = w1[(size_t)(k0 + ty + i*8) * A_DIM + a0 + tx];
    __syncthreads();
    #pragma unroll
    for (int i = 0; i < 4; i++){
        int al = ty + i*8;
        float v = t[tx][al];
        __half h = __float2half_rn(v);
        g_w1h[(size_t)(a0 + al) * D_EMB + k0 + tx] = h;
        g_w1l[(size_t)(a0 + al) * D_EMB + k0 + tx] =
            __float2half_rn(v - __half2float(h));
    }
}

// ---------------- 2: fp16x2 MMA GEMM + fused relu@w2 epilogue ------------------
// CTA 128m x 128a, 8 warps (2x4), warp tile 64x32, K chunks of 32.
// 64B rows, XOR swizzle s(r)=(r>>1)&3 (conflict-free LDSM).
// Stage = XH|WH|WL = 24KB; 4-stage cp.async pipeline, one sync per chunk.
#define ROWB   64                 // row stride in bytes (32 fp16, swizzled)
#define ARR_SZ (128*ROWB)         // 8192 B per operand array
#define STG_SZ (3*ARR_SZ)         // XH|WH|WL = 24576 B
#define NSTG   4
#define OFF_XH 0
#define OFF_WH (1*ARR_SZ)
#define OFF_WL (2*ARR_SZ)
#define OFF_C  0                            // union with stage buffers
#define C_LD   136                          // fp32 words per C row (128+8 pad)
#define OFF_W2 (NSTG*STG_SZ)                // 98304
#define SM_TOT (OFF_W2 + 128*H_H*4)         // 102400

// swizzled byte offset of (row, 16B-chunk j) within one operand array
__device__ __forceinline__ uint32_t swz(int row, int j){
    return (uint32_t)(row * ROWB + ((j ^ ((row >> 1) & 3)) << 4));
}

__device__ __forceinline__ void load_chunk(uint32_t sbuf, int c, int m0, int a0){
    const int tid = threadIdx.x;
    const int row = tid >> 1;
    const int j0  = (tid & 1) * 2;          // 16B chunks j0, j0+1
    const size_t xo = (size_t)(m0 + row) * D_EMB + c * 32;
    const size_t wo = (size_t)(a0 + row) * D_EMB + c * 32;
    #pragma unroll
    for (int j = j0; j < j0 + 2; j++){
        const uint32_t so = swz(row, j);
        cpa16(sbuf + OFF_XH + so, g_xh  + xo + j * 8);
        cpa16(sbuf + OFF_WH + so, g_w1h + wo + j * 8);
        cpa16(sbuf + OFF_WL + so, g_w1l + wo + j * 8);
    }
    cpa_commit();
}

__global__ void __launch_bounds__(256, 2) k_mma1(const float* __restrict__ w2){
    extern __shared__ char smem[];
    const uint32_t sb = smem_u32(smem);
    float* Cs  = (float*)(smem + OFF_C);
    float* W2s = (float*)(smem + OFF_W2);
    const int tid = threadIdx.x;
    const int wid = tid >> 5, lane = tid & 31;
    const int wm = wid >> 2, wn = wid & 3;       // warp grid 2x4
    const int grp = lane >> 2, t4 = lane & 3;
    const int m0 = blockIdx.x * 128;
    const int a0 = blockIdx.y * 128;

    for (int i = tid; i < 128 * H_H; i += 256)
        W2s[i] = w2[(size_t)(a0 + (i >> 3)) * H_H + (i & 7)];

    float acc[4][4][4];
    #pragma unroll
    for (int mt = 0; mt < 4; mt++)
        #pragma unroll
        for (int nt = 0; nt < 4; nt++)
            #pragma unroll
            for (int j = 0; j < 4; j++) acc[mt][nt][j] = 0.f;

    load_chunk(sb + 0*STG_SZ, 0, m0, a0);
    load_chunk(sb + 1*STG_SZ, 1, m0, a0);
    load_chunk(sb + 2*STG_SZ, 2, m0, a0);

    // ldmatrix lane addressing constants
    const int a_row = (lane & 15);          // A: row within 16-row tile
    const int a_jh  = (lane >> 4);          // A: k-half select (0/1)
    // B x4: covers nt-pair x both k-halves
    const int b_row = (lane & 7) + ((lane >> 4) << 3);
    const int b_jh  = ((lane >> 3) & 1);

    uint32_t base = sb;                     // stage 0
    for (int c = 0; c < 32; c++){
        if (c < 30) cpa_wait2(); else if (c == 30) cpa_wait1(); else cpa_wait0();
        __syncthreads();
        if (c + 3 < 32)
            load_chunk(sb + ((c + 3) % NSTG) * STG_SZ, c + 3, m0, a0);

        #pragma unroll
        for (int kk = 0; kk < 2; kk++){
            const int jb = kk * 2;          // first 16B chunk of this k16
            // frag loads: A once (reused by both terms), B hi+lo
            uint32_t ah[4][4];
            #pragma unroll
            for (int mt = 0; mt < 4; mt++){
                int r = wm * 64 + mt * 16 + a_row;
                ldm_x4(ah[mt], base + OFF_XH + swz(r, jb + a_jh));
            }
            uint32_t bh[2][4], bl[2][4];    // [np][4]: {n0k0,n0k8,n1k0,n1k8}
            #pragma unroll
            for (int np = 0; np < 2; np++){
                int r = wn * 32 + np * 16 + b_row;
                ldm_x4(bh[np], base + OFF_WH + swz(r, jb + b_jh));
            }
            #pragma unroll
            for (int np = 0; np < 2; np++){
                int r = wn * 32 + np * 16 + b_row;
                ldm_x4(bl[np], base + OFF_WL + swz(r, jb + b_jh));
            }
            // 32 MMAs: x*wh then x*wl
            #pragma unroll
            for (int mt = 0; mt < 4; mt++)
                #pragma unroll
                for (int nt = 0; nt < 4; nt++)
                    mma_f16(acc[mt][nt], ah[mt], &bh[nt >> 1][(nt & 1) * 2]);
            #pragma unroll
            for (int mt = 0; mt < 4; mt++)
                #pragma unroll
                for (int nt = 0; nt < 4; nt++)
                    mma_f16(acc[mt][nt], ah[mt], &bl[nt >> 1][(nt & 1) * 2]);
        }
        base = sb + ((c + 1) % NSTG) * STG_SZ;
    }
    __syncthreads();   // all warps done reading buffers before C overwrites them

    // relu(C) -> smem (union region)
    #pragma unroll
    for (int mt = 0; mt < 4; mt++)
        #pragma unroll
        for (int nt = 0; nt < 4; nt++){
            const int r0 = wm * 64 + mt * 16 + grp;
            const int c0 = wn * 32 + nt * 8 + t4 * 2;
            Cs[(r0    ) * C_LD + c0    ] = fmaxf(acc[mt][nt][0], 0.f);
            Cs[(r0    ) * C_LD + c0 + 1] = fmaxf(acc[mt][nt][1], 0.f);
            Cs[(r0 + 8) * C_LD + c0    ] = fmaxf(acc[mt][nt][2], 0.f);
            Cs[(r0 + 8) * C_LD + c0 + 1] = fmaxf(acc[mt][nt][3], 0.f);
        }
    __syncthreads();

    // h partial: relu(C)[128x128] @ w2slice[128x8]
    #pragma unroll
    for (int it = 0; it < 4; it++){
        const int idx = tid + it * 256;
        const int row = idx >> 3, h = idx & 7;
        float s = 0.f;
        #pragma unroll 8
        for (int cc = 0; cc < 128; cc++)
            s = fmaf(Cs[row * C_LD + cc], W2s[cc * H_H + h], s);
        g_hpart[blockIdx.y][(size_t)(m0 + row) * H_H + h] = s;
    }
}

// ---------------- 3: per-segment softmax (combines 16 partials) ---------------
__global__ __launch_bounds__(256) void k_softmax(){
    const int b = blockIdx.x, tid = threadIdx.x;
    const int start = g_segstart[b];
    const int len = g_segstart[b+1] - start;
    __shared__ float red[256 * H_H];
    __shared__ float mval[H_H], sval[H_H];

    float lm[H_H];
    #pragma unroll
    for (int h = 0; h < H_H; h++) lm[h] = -1e30f;
    for (int r = tid; r < len; r += 256){
        const int n = start + r;
        #pragma unroll
        for (int h = 0; h < H_H; h++){
            float v = 0.f;
            #pragma unroll
            for (int p = 0; p < NTA; p++) v += g_hpart[p][(size_t)n*H_H + h];
            g_h[(size_t)n*H_H + h] = v;
            lm[h] = fmaxf(lm[h], v);
        }
    }
    #pragma unroll
    for (int h = 0; h < H_H; h++) red[tid*H_H + h] = lm[h];
    __syncthreads();
    for (int off = 128; off > 0; off >>= 1){
        if (tid < off)
            #pragma unroll
            for (int h = 0; h < H_H; h++)
                red[tid*H_H+h] = fmaxf(red[tid*H_H+h], red[(tid+off)*H_H+h]);
        __syncthreads();
    }
    if (tid < H_H) mval[tid] = red[tid];
    __syncthreads();

    float ls[H_H];
    #pragma unroll
    for (int h = 0; h < H_H; h++) ls[h] = 0.f;
    for (int r = tid; r < len; r += 256){
        const int n = start + r;
        #pragma unroll
        for (int h = 0; h < H_H; h++) ls[h] += expf(g_h[(size_t)n*H_H+h] - mval[h]);
    }
    #pragma unroll
    for (int h = 0; h < H_H; h++) red[tid*H_H + h] = ls[h];
    __syncthreads();
    for (int off = 128; off > 0; off >>= 1){
        if (tid < off)
            #pragma unroll
            for (int h = 0; h < H_H; h++)
                red[tid*H_H+h] += red[(tid+off)*H_H+h];
        __syncthreads();
    }
    if (tid < H_H) sval[tid] = red[tid];
    __syncthreads();

    float inv[H_H];
    #pragma unroll
    for (int h = 0; h < H_H; h++) inv[h] = 1.f / sval[h];
    for (int r = tid; r < len; r += 256){
        const int n = start + r;
        #pragma unroll
        for (int h = 0; h < H_H; h++)
            g_attn[(size_t)n*H_H+h] = expf(g_h[(size_t)n*H_H+h] - mval[h]) * inv[h];
    }
}

// ---------------- 4: pooling split over rows -----------------------------------
__global__ __launch_bounds__(256) void k_pool(const float* __restrict__ x){
    const int b = blockIdx.x;
    const int d = blockIdx.y * 256 + threadIdx.x;
    const int chunk = blockIdx.z;
    const int start = g_segstart[b];
    const int len = g_segstart[b+1] - start;
    const int cl = (len + PSPL - 1) / PSPL;
    const int r0b = chunk * cl;
    const int r1b = min(len, r0b + cl);

    __shared__ float sat[32][H_H];
    float acc[H_H];
    #pragma unroll
    for (int h = 0; h < H_H; h++) acc[h] = 0.f;
    float ssum = 0.f;

    for (int r0 = r0b; r0 < r1b; r0 += 32){
        const int cnt = min(32, r1b - r0);
        if (threadIdx.x < cnt * H_H){
            const int rr = threadIdx.x >> 3, hh = threadIdx.x & 7;
            sat[rr][hh] = g_attn[(size_t)(start + r0 + rr) * H_H + hh];
        }
        __syncthreads();
        for (int rr = 0; rr < cnt; rr++){
            const float xv = x[(size_t)(start + r0 + rr) * D_EMB + d];
            ssum += xv;
            #pragma unroll
            for (int h = 0; h < H_H; h++) acc[h] = fmaf(xv, sat[rr][h], acc[h]);
        }
        __syncthreads();
    }
    #pragma unroll
    for (int h = 0; h < H_H; h++)
        g_poolpart[chunk][(size_t)b * DH + d * H_H + h] = acc[h];
    g_msumpart[chunk][(size_t)b * D_EMB + d] = ssum;
}

__global__ __launch_bounds__(256) void k_poolred(float* __restrict__ out){
    const int i = blockIdx.x * 256 + threadIdx.x;   // 65536
    const int b = i >> 10, d = i & 1023;
    float acc[H_H];
    #pragma unroll
    for (int h = 0; h < H_H; h++) acc[h] = 0.f;
    float s = 0.f;
    #pragma unroll
    for (int p = 0; p < PSPL; p++){
        #pragma unroll
        for (int h = 0; h < H_H; h++)
            acc[h] += g_poolpart[p][(size_t)b * DH + d * H_H + h];
        s += g_msumpart[p][(size_t)b * D_EMB + d];
    }
    #pragma unroll
    for (int h = 0; h < H_H; h++)
        g_obdh[(size_t)b * DH + d * H_H + h] = acc[h];
    const int len = g_segstart[b+1] - g_segstart[b];
    out[B_SEG * D_EMB + i] = s / (float)len;
}

// ---------------- 5: attn gram --------------------------------------------------
__global__ void k_gram(float* __restrict__ out){
    const int b = blockIdx.x, tid = threadIdx.x;   // 64
    const int i = tid >> 3, j = tid & 7;
    const int start = g_segstart[b];
    const int len = g_segstart[b+1] - start;
    float acc = 0.f;
    for (int r = 0; r < len; r++){
        const float* a = &g_attn[(size_t)(start + r) * H_H];
        acc = fmaf(a[i], a[j], acc);
    }
    out[2 * B_SEG * D_EMB + b * 64 + tid] = acc;
}

// ---------------- 6: post GEMM (64x1024x8192) -----------------------------------
__global__ __launch_bounds__(256) void k_post(const float* __restrict__ wp){
    __shared__ float As[16][72];
    __shared__ float Ws[16][72];
    const int tid = threadIdx.x;
    const int tx = tid & 15, ty = tid >> 4;
    const int j0 = blockIdx.x * 64;
    const int ks = blockIdx.y;
    const int kbase = ks * 1024;

    float acc[4][4];
    #pragma unroll
    for (int i = 0; i < 4; i++)
        #pragma unroll
        for (int j = 0; j < 4; j++) acc[i][j] = 0.f;

    for (int kc = 0; kc < 64; kc++){
        const int k0 = kbase + kc * 16;
        {
            const int row = tid >> 2, q = tid & 3;
            float4 v = *(const float4*)&g_obdh[(size_t)row * DH + k0 + q * 4];
            As[q*4+0][row] = v.x; As[q*4+1][row] = v.y;
            As[q*4+2][row] = v.z; As[q*4+3][row] = v.w;
        }
        {
            const int row = tid >> 4, q = tid & 15;
            float4 v = *(const float4*)&wp[(size_t)(k0 + row) * D_EMB + j0 + q * 4];
            *(float4*)&Ws[row][q * 4] = v;
        }
        __syncthreads();
        #pragma unroll
        for (int k = 0; k < 16; k++){
            float4 av = *(const float4*)&As[k][ty * 4];
            float4 wv = *(const float4*)&Ws[k][tx * 4];
            float ar[4] = {av.x, av.y, av.z, av.w};
            float wr[4] = {wv.x, wv.y, wv.z, wv.w};
            #pragma unroll
            for (int i = 0; i < 4; i++)
                #pragma unroll
                for (int j = 0; j < 4; j++)
                    acc[i][j] = fmaf(ar[i], wr[j], acc[i][j]);
        }
        __syncthreads();
    }
    #pragma unroll
    for (int i = 0; i < 4; i++)
        #pragma unroll
        for (int j = 0; j < 4; j++)
            g_outpart[ks][(size_t)(ty*4 + i) * D_EMB + j0 + tx*4 + j] = acc[i][j];
}

__global__ void k_redout(float* __restrict__ out){
    const int i = blockIdx.x * 256 + threadIdx.x;
    float s = 0.f;
    #pragma unroll
    for (int p = 0; p < 8; p++) s += g_outpart[p][i];
    out[i] = s;
}

// ---------------- launch ----------------------------------------------------------
extern "C" void kernel_launch(void* const* d_in, const int* in_sizes, int n_in,
                              void* d_out, int out_size)
{
    const float* x   = (const float*)d_in[0];
    const int*   seg = (const int*)  d_in[1];
    const float* w1  = (const float*)d_in[2];
    const float* w2  = (const float*)d_in[3];
    const float* wp  = (const float*)d_in[4];
    float* out = (float*)d_out;

    cudaFuncSetAttribute(k_mma1, cudaFuncAttributeMaxDynamicSharedMemorySize, SM_TOT);

    k_prefix  <<<1, 32>>>(seg);
    k_splitx  <<<N_FR*D_EMB/1024, 256>>>(x);
    k_splitw  <<<dim3(A_DIM/32, D_EMB/32), dim3(32, 8)>>>(w1);
    k_mma1    <<<dim3(N_FR/128, NTA), 256, SM_TOT>>>(w2);
    k_softmax <<<B_SEG, 256>>>();
    k_pool    <<<dim3(B_SEG, 4, PSPL), 256>>>(x);
    k_poolred <<<B_SEG*D_EMB/256, 256>>>(out);
    k_gram    <<<B_SEG, 64>>>(out);
    k_post    <<<dim3(16, 8), 256>>>(wp);
    k_redout  <<<B_SEG*D_EMB/256, 256>>>(out);
}